// round 5
// baseline (speedup 1.0000x reference)
#include <cuda_runtime.h>
#include <cstdint>

// Problem dims (fixed by the reference)
#define BSZ   2
#define LEN   1024
#define DM    1024
#define DI    2048
#define DS    16
#define DR    64
#define MROWS (BSZ*LEN)     // 2048

// ---------------------------------------------------------------------------
// Scratch (allocation-free: __device__ globals)
// ---------------------------------------------------------------------------
__device__ float g_xz  [MROWS * 2 * DI];   // in_proj output (x | z)
__device__ float g_x   [MROWS * DI];       // conv + silu output
__device__ float g_xdbl[MROWS * 96];       // x_proj output (dt_r | B | C)
__device__ float g_dt  [MROWS * DI];       // softplus(dt)
__device__ float g_y   [MROWS * DI];       // scan output (gated)

__device__ __forceinline__ uint32_t f2tf(float x) {
    uint32_t r;
    asm("cvt.rna.tf32.f32 %0, %1;" : "=r"(r) : "f"(x));
    return r;
}

__device__ __forceinline__ void cpa16(void* dst, const void* src, int sz) {
    uint32_t d = (uint32_t)__cvta_generic_to_shared(dst);
    asm volatile("cp.async.cg.shared.global [%0], [%1], 16, %2;\n"
                 :: "r"(d), "l"(src), "r"(sz) : "memory");
}

// ---------------------------------------------------------------------------
// tf32 tensor-core GEMM v4:  C[M,N] (+)= A[M,K-slice] * W[N,K-slice]^T
// Block tile 64x64, 128 threads = 4 warps (2m x 2n), warp tile 32x32.
// 4-stage cp.async pipeline, smem holds raw fp32, cvt->tf32 at frag load.
// Small tile => big grids + ~5 CTAs/SM => high issue occupancy.
// grid.z splits K (ksplit per z); atomic=1 -> atomicAdd epilogue.
// act==1: C = softplus(C + bias[n]).
// M % 64 == 0, ksplit % 16 == 0, ksplit >= 64 required (true at call sites).
// ---------------------------------------------------------------------------
#define NS 4
__global__ void __launch_bounds__(128, 5) gemm_v4(
    const float* __restrict__ A, int lda,
    const float* __restrict__ W, int ldw,
    float* __restrict__ C, int ldc,
    int N, int ksplit,
    const float* __restrict__ bias, int act, int atomic)
{
    __shared__ float As[NS][64][20];   // pad 20 -> conflict-free frag reads
    __shared__ float Ws[NS][64][20];

    const int bm   = blockIdx.y * 64;
    const int bn   = blockIdx.x * 64;
    const int kb   = blockIdx.z * ksplit;
    const int tid  = threadIdx.x;
    const int warp = tid >> 5;
    const int lane = tid & 31;
    const int wm   = (warp & 1) * 32;
    const int wn   = (warp >> 1) * 32;
    const int g    = lane >> 2;   // group id 0..7
    const int tg   = lane & 3;    // thread-in-group 0..3

    // loader mapping: thread covers rows (r0, r0+32), 16B chunk at col c4
    const int r0 = tid >> 2;          // 0..31
    const int c4 = (tid & 3) * 4;     // 0,4,8,12
    const int wsz0 = (bn + r0      < N) ? 16 : 0;
    const int wsz1 = (bn + r0 + 32 < N) ? 16 : 0;
    const float* a0p = &A[(bm + r0)      * lda + kb + c4];
    const float* a1p = &A[(bm + r0 + 32) * lda + kb + c4];
    const float* w0p = &W[(bn + r0)      * ldw + kb + c4];
    const float* w1p = &W[(bn + r0 + 32) * ldw + kb + c4];

    float acc[2][4][4];
#pragma unroll
    for (int i = 0; i < 2; i++)
#pragma unroll
        for (int j = 0; j < 4; j++)
#pragma unroll
            for (int c = 0; c < 4; c++) acc[i][j][c] = 0.f;

    const int nstage = ksplit >> 4;

    // prologue: issue stages 0..NS-2
#pragma unroll
    for (int s = 0; s < NS - 1; s++) {
        const int ko = s * 16;
        cpa16(&As[s][r0][c4],      a0p + ko, 16);
        cpa16(&As[s][r0 + 32][c4], a1p + ko, 16);
        cpa16(&Ws[s][r0][c4],      w0p + ko, wsz0);
        cpa16(&Ws[s][r0 + 32][c4], w1p + ko, wsz1);
        asm volatile("cp.async.commit_group;\n" ::: "memory");
    }

    for (int s = 0; s < nstage; s++) {
        const int buf = s & (NS - 1);

        if (s + NS - 1 < nstage) {
            const int nb = (s + NS - 1) & (NS - 1);
            const int ko = (s + NS - 1) * 16;
            cpa16(&As[nb][r0][c4],      a0p + ko, 16);
            cpa16(&As[nb][r0 + 32][c4], a1p + ko, 16);
            cpa16(&Ws[nb][r0][c4],      w0p + ko, wsz0);
            cpa16(&Ws[nb][r0 + 32][c4], w1p + ko, wsz1);
        }
        asm volatile("cp.async.commit_group;\n" ::: "memory");   // uniform count
        asm volatile("cp.async.wait_group %0;\n" :: "n"(NS - 1) : "memory");
        __syncthreads();

        const float (*as)[20] = As[buf];
        const float (*ws)[20] = Ws[buf];
#pragma unroll
        for (int kk = 0; kk < 16; kk += 8) {
            uint32_t af[2][4], bf[4][2];
#pragma unroll
            for (int mf = 0; mf < 2; mf++) {
                const int row = wm + mf * 16 + g;
                af[mf][0] = f2tf(as[row][kk + tg]);
                af[mf][1] = f2tf(as[row + 8][kk + tg]);
                af[mf][2] = f2tf(as[row][kk + tg + 4]);
                af[mf][3] = f2tf(as[row + 8][kk + tg + 4]);
            }
#pragma unroll
            for (int jf = 0; jf < 4; jf++) {
                const int col = wn + jf * 8 + g;
                bf[jf][0] = f2tf(ws[col][kk + tg]);
                bf[jf][1] = f2tf(ws[col][kk + tg + 4]);
            }
#pragma unroll
            for (int mf = 0; mf < 2; mf++)
#pragma unroll
                for (int jf = 0; jf < 4; jf++)
                    asm volatile(
                        "mma.sync.aligned.m16n8k8.row.col.f32.tf32.tf32.f32 "
                        "{%0,%1,%2,%3},{%4,%5,%6,%7},{%8,%9},{%0,%1,%2,%3};"
                        : "+f"(acc[mf][jf][0]), "+f"(acc[mf][jf][1]),
                          "+f"(acc[mf][jf][2]), "+f"(acc[mf][jf][3])
                        : "r"(af[mf][0]), "r"(af[mf][1]),
                          "r"(af[mf][2]), "r"(af[mf][3]),
                          "r"(bf[jf][0]), "r"(bf[jf][1]));
        }
        __syncthreads();
    }

    // ---- epilogue
#pragma unroll
    for (int mf = 0; mf < 2; mf++)
#pragma unroll
        for (int jf = 0; jf < 4; jf++) {
            const int nn = bn + wn + jf * 8 + tg * 2;
            if (nn < N) {
                const int m0 = bm + wm + mf * 16 + g;
                float v0 = acc[mf][jf][0], v1 = acc[mf][jf][1];
                float v2 = acc[mf][jf][2], v3 = acc[mf][jf][3];
                if (act) {
                    const float b0 = bias[nn], b1 = bias[nn + 1];
                    v0 += b0; v1 += b1; v2 += b0; v3 += b1;
                    v0 = (v0 > 20.f) ? v0 : log1pf(__expf(v0));
                    v1 = (v1 > 20.f) ? v1 : log1pf(__expf(v1));
                    v2 = (v2 > 20.f) ? v2 : log1pf(__expf(v2));
                    v3 = (v3 > 20.f) ? v3 : log1pf(__expf(v3));
                }
                if (atomic) {
                    atomicAdd(&C[m0 * ldc + nn],           v0);
                    atomicAdd(&C[m0 * ldc + nn + 1],       v1);
                    atomicAdd(&C[(m0 + 8) * ldc + nn],     v2);
                    atomicAdd(&C[(m0 + 8) * ldc + nn + 1], v3);
                } else {
                    *(float2*)&C[m0 * ldc + nn]       = make_float2(v0, v1);
                    *(float2*)&C[(m0 + 8) * ldc + nn] = make_float2(v2, v3);
                }
            }
        }
}

// ---------------------------------------------------------------------------
__global__ void zero_kernel(float* __restrict__ p, int n)
{
    int i = blockIdx.x * 256 + threadIdx.x;
    if (i < n) p[i] = 0.f;
}

// ---------------------------------------------------------------------------
// Depthwise causal conv (K=4) + bias + SiLU.  Reads x-part of g_xz -> g_x.
// ---------------------------------------------------------------------------
__global__ void conv_silu_kernel(const float* __restrict__ xz,
                                 const float* __restrict__ w,
                                 const float* __restrict__ bias,
                                 float* __restrict__ xout)
{
    int idx = blockIdx.x * blockDim.x + threadIdx.x;   // over MROWS*DI
    int d  = idx & (DI - 1);
    int bl = idx >> 11;                                // (b*L + l)
    int l  = bl & (LEN - 1);
    float accv = bias[d];
#pragma unroll
    for (int k = 0; k < 4; k++) {
        int ll = l + k - 3;
        if (ll >= 0)
            accv += xz[(bl + (ll - l)) * (2 * DI) + d] * w[d * 4 + k];
    }
    xout[idx] = accv / (1.f + __expf(-accv));
}

// ---------------------------------------------------------------------------
// Selective scan + fused gating. Block = 256 threads = 16 d-channels, one b.
// warp: 2 d-channels x 16 states. Chunks of 128 steps staged in smem.
// ---------------------------------------------------------------------------
#define LC 128
__global__ void __launch_bounds__(256) scan_kernel(
    const float* __restrict__ dtp,   // g_dt
    const float* __restrict__ xp,    // g_x
    const float* __restrict__ xdbl,  // g_xdbl (B at col 64, C at col 80)
    const float* __restrict__ A_log,
    const float* __restrict__ Dp,
    const float* __restrict__ xz,    // for z-gate
    float* __restrict__ y)
{
    __shared__ float sB[LC][DS];
    __shared__ float sC[LC][DS];
    __shared__ float sdt[LC][16];
    __shared__ float sx[LC][16];

    const int b   = blockIdx.x / (DI / 16);
    const int d0  = (blockIdx.x % (DI / 16)) * 16;
    const int tid = threadIdx.x;
    const int warp = tid >> 5, lane = tid & 31;
    const int sub = lane >> 4, n = lane & 15;
    const int dl  = warp * 2 + sub;      // 0..15
    const int d   = d0 + dl;

    const float a  = -__expf(A_log[d * DS + n]);
    const float Dv = Dp[d];
    float h = 0.f;

    for (int c = 0; c < LEN / LC; c++) {
        __syncthreads();
        for (int e = tid; e < LC * DS; e += 256) {
            int t = e >> 4, nn = e & 15;
            const float* row = &xdbl[(b * LEN + c * LC + t) * 96];
            sB[t][nn] = row[64 + nn];
            sC[t][nn] = row[80 + nn];
        }
        for (int e = tid; e < LC * 16; e += 256) {
            int t = e >> 4, dd = e & 15;
            int gi = (b * LEN + c * LC + t) * DI + d0 + dd;
            sdt[t][dd] = dtp[gi];
            sx[t][dd]  = xp[gi];
        }
        __syncthreads();

        for (int t = 0; t < LC; t++) {
            float dt = sdt[t][dl];
            float xv = sx[t][dl];
            float dA = __expf(dt * a);
            h = fmaf(dA, h, dt * sB[t][n] * xv);
            float part = h * sC[t][n];
            part += __shfl_xor_sync(0xffffffffu, part, 8);
            part += __shfl_xor_sync(0xffffffffu, part, 4);
            part += __shfl_xor_sync(0xffffffffu, part, 2);
            part += __shfl_xor_sync(0xffffffffu, part, 1);
            if (n == 0) {
                int bl = b * LEN + c * LC + t;
                float z = xz[bl * (2 * DI) + DI + d];
                float gz = z / (1.f + __expf(-z));
                y[bl * DI + d] = (part + xv * Dv) * gz;
            }
        }
    }
}

// ---------------------------------------------------------------------------
extern "C" void kernel_launch(void* const* d_in, const int* in_sizes, int n_in,
                              void* d_out, int out_size)
{
    const float* hidden = (const float*)d_in[0];
    const float* in_w   = (const float*)d_in[1];
    const float* conv_w = (const float*)d_in[2];
    const float* conv_b = (const float*)d_in[3];
    const float* xproj  = (const float*)d_in[4];
    const float* dtw    = (const float*)d_in[5];
    const float* dtb    = (const float*)d_in[6];
    const float* alog   = (const float*)d_in[7];
    const float* Dp     = (const float*)d_in[8];
    const float* outw   = (const float*)d_in[9];
    float* out = (float*)d_out;

    static float *pxz = nullptr, *px = nullptr, *pxd = nullptr,
                 *pdt = nullptr, *py = nullptr;
    if (!pxz) {
        cudaGetSymbolAddress((void**)&pxz, g_xz);
        cudaGetSymbolAddress((void**)&px,  g_x);
        cudaGetSymbolAddress((void**)&pxd, g_xdbl);
        cudaGetSymbolAddress((void**)&pdt, g_dt);
        cudaGetSymbolAddress((void**)&py,  g_y);
    }

    // 1) xz = hidden @ in_proj_w^T          (2048 x 4096 x 1024)
    gemm_v4<<<dim3(2 * DI / 64, MROWS / 64, 1), 128>>>(
        hidden, DM, in_w, DM, pxz, 2 * DI, 2 * DI, DM, nullptr, 0, 0);

    // 2) x = silu(conv1d(x) + b)
    conv_silu_kernel<<<(MROWS * DI) / 256, 256>>>(pxz, conv_w, conv_b, px);

    // 3) x_dbl = x @ x_proj_w^T             (2048 x 96 x 2048), split-K=4
    zero_kernel<<<(MROWS * 96 + 255) / 256, 256>>>(pxd, MROWS * 96);
    gemm_v4<<<dim3(2, MROWS / 64, 4), 128>>>(
        px, DI, xproj, DI, pxd, 96, 96, DI / 4, nullptr, 0, 1);

    // 4) dt = softplus(x_dbl[:, :64] @ dt_proj_w^T + b)   (2048 x 2048 x 64)
    gemm_v4<<<dim3(DI / 64, MROWS / 64, 1), 128>>>(
        pxd, 96, dtw, DR, pdt, DI, DI, DR, dtb, 1, 0);

    // 5) selective scan -> y (includes + x*D and *silu(z))
    scan_kernel<<<BSZ * (DI / 16), 256>>>(pdt, px, pxd, alog, Dp, pxz, py);

    // 6) out = y @ out_proj_w^T             (2048 x 1024 x 2048)
    gemm_v4<<<dim3(DM / 64, MROWS / 64, 1), 128>>>(
        py, DI, outw, DI, out, DM, DM, DI, nullptr, 0, 0);
}

// round 6
// speedup vs baseline: 1.0592x; 1.0592x over previous
#include <cuda_runtime.h>
#include <cuda_fp16.h>
#include <cstdint>

// Problem dims (fixed by the reference)
#define BSZ   2
#define LEN   1024
#define DM    1024
#define DI    2048
#define DS    16
#define DR    64
#define MROWS (BSZ*LEN)     // 2048

// ---------------------------------------------------------------------------
// Scratch (allocation-free: __device__ globals)
// ---------------------------------------------------------------------------
__device__ float  g_xz   [MROWS * 2 * DI];  // in_proj out (x | z), fp32
__device__ float  g_x    [MROWS * DI];      // conv+silu out fp32 (scan)
__device__ __half g_xh   [MROWS * DI];      // conv+silu out half (x_proj A)
__device__ float  g_xdbl [MROWS * 96];      // x_proj out (dt_r | B | C) fp32
__device__ __half g_dtrh [MROWS * DR];      // x_dbl[:, :64] in half (dt_proj A)
__device__ float  g_dt   [MROWS * DI];      // softplus dt fp32
__device__ __half g_yh   [MROWS * DI];      // gated scan out half (out_proj A)

__device__ __half g_hidh [MROWS * DM];      // hidden in half
__device__ __half g_inwh [2 * DI * DM];     // in_proj_w half
__device__ __half g_xpwh [96 * DI];         // x_proj_w half
__device__ __half g_dtwh [DI * DR];         // dt_proj_w half
__device__ __half g_otwh [DM * DI];         // out_proj_w half

__device__ __forceinline__ void cpa16(void* dst, const void* src, int sz) {
    uint32_t d = (uint32_t)__cvta_generic_to_shared(dst);
    asm volatile("cp.async.cg.shared.global [%0], [%1], 16, %2;\n"
                 :: "r"(d), "l"(src), "r"(sz) : "memory");
}

// ---------------------------------------------------------------------------
// fp16 tensor-core GEMM:  C[M,N] (+)= A[M,Kslice] * W[N,Kslice]^T  (fp32 acc)
// Block tile 64x64, 128 threads = 4 warps (2m x 2n), warp tile 32x32.
// mma.m16n8k16.f32.f16.f16.f32; 4-stage cp.async pipeline; smem 24.6KB.
// grid.z splits K; atomic=1 -> atomicAdd epilogue; act==1 -> softplus(+bias).
// M%64==0, ksplit%16==0, nstage>=NS-1 required (true at all call sites).
// ---------------------------------------------------------------------------
#define NS 4
__global__ void __launch_bounds__(128, 6) gemm_h(
    const __half* __restrict__ A, int lda,
    const __half* __restrict__ W, int ldw,
    float* __restrict__ C, int ldc,
    int N, int ksplit,
    const float* __restrict__ bias, int act, int atomic)
{
    __shared__ __half As[NS][64][24];   // stride 24 halfs (48B): conflict-free
    __shared__ __half Ws[NS][64][24];

    const int bm   = blockIdx.y * 64;
    const int bn   = blockIdx.x * 64;
    const int kb   = blockIdx.z * ksplit;
    const int tid  = threadIdx.x;
    const int warp = tid >> 5;
    const int lane = tid & 31;
    const int wm   = (warp & 1) * 32;
    const int wn   = (warp >> 1) * 32;
    const int g    = lane >> 2;   // 0..7
    const int tg   = lane & 3;    // 0..3

    // loader: each thread one 16B chunk per matrix per stage
    const int r  = tid >> 1;           // 0..63
    const int c8 = (tid & 1) * 8;      // 0 or 8 (halfs)
    const int wsz = (bn + r < N) ? 16 : 0;
    const __half* ap = &A[(bm + r) * lda + kb + c8];
    const __half* wp = &W[(bn + r) * ldw + kb + c8];

    float acc[2][4][4];
#pragma unroll
    for (int i = 0; i < 2; i++)
#pragma unroll
        for (int j = 0; j < 4; j++)
#pragma unroll
            for (int c = 0; c < 4; c++) acc[i][j][c] = 0.f;

    const int nstage = ksplit >> 4;

#pragma unroll
    for (int s = 0; s < NS - 1; s++) {
        cpa16(&As[s][r][c8], ap + s * 16, 16);
        cpa16(&Ws[s][r][c8], wp + s * 16, wsz);
        asm volatile("cp.async.commit_group;\n" ::: "memory");
    }

    for (int s = 0; s < nstage; s++) {
        const int buf = s & (NS - 1);
        if (s + NS - 1 < nstage) {
            const int nb = (s + NS - 1) & (NS - 1);
            const int ko = (s + NS - 1) * 16;
            cpa16(&As[nb][r][c8], ap + ko, 16);
            cpa16(&Ws[nb][r][c8], wp + ko, wsz);
        }
        asm volatile("cp.async.commit_group;\n" ::: "memory");
        asm volatile("cp.async.wait_group %0;\n" :: "n"(NS - 1) : "memory");
        __syncthreads();

        const __half (*as)[24] = As[buf];
        const __half (*ws)[24] = Ws[buf];

        uint32_t af[2][4], bf[4][2];
#pragma unroll
        for (int mf = 0; mf < 2; mf++) {
            const int row = wm + mf * 16 + g;
            af[mf][0] = *(const uint32_t*)&as[row][2 * tg];
            af[mf][1] = *(const uint32_t*)&as[row + 8][2 * tg];
            af[mf][2] = *(const uint32_t*)&as[row][2 * tg + 8];
            af[mf][3] = *(const uint32_t*)&as[row + 8][2 * tg + 8];
        }
#pragma unroll
        for (int jf = 0; jf < 4; jf++) {
            const int col = wn + jf * 8 + g;
            bf[jf][0] = *(const uint32_t*)&ws[col][2 * tg];
            bf[jf][1] = *(const uint32_t*)&ws[col][2 * tg + 8];
        }
#pragma unroll
        for (int mf = 0; mf < 2; mf++)
#pragma unroll
            for (int jf = 0; jf < 4; jf++)
                asm volatile(
                    "mma.sync.aligned.m16n8k16.row.col.f32.f16.f16.f32 "
                    "{%0,%1,%2,%3},{%4,%5,%6,%7},{%8,%9},{%0,%1,%2,%3};"
                    : "+f"(acc[mf][jf][0]), "+f"(acc[mf][jf][1]),
                      "+f"(acc[mf][jf][2]), "+f"(acc[mf][jf][3])
                    : "r"(af[mf][0]), "r"(af[mf][1]),
                      "r"(af[mf][2]), "r"(af[mf][3]),
                      "r"(bf[jf][0]), "r"(bf[jf][1]));
        __syncthreads();
    }

    // ---- epilogue
#pragma unroll
    for (int mf = 0; mf < 2; mf++)
#pragma unroll
        for (int jf = 0; jf < 4; jf++) {
            const int nn = bn + wn + jf * 8 + tg * 2;
            if (nn < N) {
                const int m0 = bm + wm + mf * 16 + g;
                float v0 = acc[mf][jf][0], v1 = acc[mf][jf][1];
                float v2 = acc[mf][jf][2], v3 = acc[mf][jf][3];
                if (act) {
                    const float b0 = bias[nn], b1 = bias[nn + 1];
                    v0 += b0; v1 += b1; v2 += b0; v3 += b1;
                    v0 = (v0 > 20.f) ? v0 : log1pf(__expf(v0));
                    v1 = (v1 > 20.f) ? v1 : log1pf(__expf(v1));
                    v2 = (v2 > 20.f) ? v2 : log1pf(__expf(v2));
                    v3 = (v3 > 20.f) ? v3 : log1pf(__expf(v3));
                }
                if (atomic) {
                    atomicAdd(&C[m0 * ldc + nn],           v0);
                    atomicAdd(&C[m0 * ldc + nn + 1],       v1);
                    atomicAdd(&C[(m0 + 8) * ldc + nn],     v2);
                    atomicAdd(&C[(m0 + 8) * ldc + nn + 1], v3);
                } else {
                    *(float2*)&C[m0 * ldc + nn]       = make_float2(v0, v1);
                    *(float2*)&C[(m0 + 8) * ldc + nn] = make_float2(v2, v3);
                }
            }
        }
}

// ---------------------------------------------------------------------------
__global__ void f2h_kernel(const float* __restrict__ s, __half* __restrict__ d, int n)
{
    int i = blockIdx.x * 512 + threadIdx.x;
    if (i < n) d[i] = __float2half_rn(s[i]);
}

__global__ void dtr2h_kernel(const float* __restrict__ xdbl, __half* __restrict__ d)
{
    int i = blockIdx.x * 512 + threadIdx.x;   // over MROWS*DR
    if (i < MROWS * DR) {
        int r = i >> 6, c = i & 63;
        d[i] = __float2half_rn(xdbl[r * 96 + c]);
    }
}

__global__ void zero_kernel(float* __restrict__ p, int n)
{
    int i = blockIdx.x * 512 + threadIdx.x;
    if (i < n) p[i] = 0.f;
}

// ---------------------------------------------------------------------------
// Depthwise causal conv (K=4) + bias + SiLU. Writes fp32 (scan) + half (GEMM).
// ---------------------------------------------------------------------------
__global__ void conv_silu_kernel(const float* __restrict__ xz,
                                 const float* __restrict__ w,
                                 const float* __restrict__ bias,
                                 float* __restrict__ xout,
                                 __half* __restrict__ xhout)
{
    int idx = blockIdx.x * blockDim.x + threadIdx.x;   // over MROWS*DI
    int d  = idx & (DI - 1);
    int bl = idx >> 11;                                // (b*L + l)
    int l  = bl & (LEN - 1);
    float accv = bias[d];
#pragma unroll
    for (int k = 0; k < 4; k++) {
        int ll = l + k - 3;
        if (ll >= 0)
            accv += xz[(bl + (ll - l)) * (2 * DI) + d] * w[d * 4 + k];
    }
    float v = accv / (1.f + __expf(-accv));
    xout[idx]  = v;
    xhout[idx] = __float2half_rn(v);
}

// ---------------------------------------------------------------------------
// Selective scan + fused gating. Block = 256 threads = 16 d-channels, one b.
// warp: 2 d-channels x 16 states. Chunks of 128 steps staged in smem.
// Writes gated output as half for out_proj.
// ---------------------------------------------------------------------------
#define LC 128
__global__ void __launch_bounds__(256) scan_kernel(
    const float* __restrict__ dtp,   // g_dt
    const float* __restrict__ xp,    // g_x (fp32)
    const float* __restrict__ xdbl,  // g_xdbl (B at col 64, C at col 80)
    const float* __restrict__ A_log,
    const float* __restrict__ Dp,
    const float* __restrict__ xz,    // z-gate (fp32)
    __half* __restrict__ y)
{
    __shared__ float sB[LC][DS];
    __shared__ float sC[LC][DS];
    __shared__ float sdt[LC][16];
    __shared__ float sx[LC][16];

    const int b   = blockIdx.x / (DI / 16);
    const int d0  = (blockIdx.x % (DI / 16)) * 16;
    const int tid = threadIdx.x;
    const int warp = tid >> 5, lane = tid & 31;
    const int sub = lane >> 4, n = lane & 15;
    const int dl  = warp * 2 + sub;      // 0..15
    const int d   = d0 + dl;

    const float a  = -__expf(A_log[d * DS + n]);
    const float Dv = Dp[d];
    float h = 0.f;

    for (int c = 0; c < LEN / LC; c++) {
        __syncthreads();
        for (int e = tid; e < LC * DS; e += 256) {
            int t = e >> 4, nn = e & 15;
            const float* row = &xdbl[(b * LEN + c * LC + t) * 96];
            sB[t][nn] = row[64 + nn];
            sC[t][nn] = row[80 + nn];
        }
        for (int e = tid; e < LC * 16; e += 256) {
            int t = e >> 4, dd = e & 15;
            int gi = (b * LEN + c * LC + t) * DI + d0 + dd;
            sdt[t][dd] = dtp[gi];
            sx[t][dd]  = xp[gi];
        }
        __syncthreads();

        for (int t = 0; t < LC; t++) {
            float dt = sdt[t][dl];
            float xv = sx[t][dl];
            float dA = __expf(dt * a);
            h = fmaf(dA, h, dt * sB[t][n] * xv);
            float part = h * sC[t][n];
            part += __shfl_xor_sync(0xffffffffu, part, 8);
            part += __shfl_xor_sync(0xffffffffu, part, 4);
            part += __shfl_xor_sync(0xffffffffu, part, 2);
            part += __shfl_xor_sync(0xffffffffu, part, 1);
            if (n == 0) {
                int bl = b * LEN + c * LC + t;
                float z = xz[bl * (2 * DI) + DI + d];
                float gz = z / (1.f + __expf(-z));
                y[bl * DI + d] = __float2half_rn((part + xv * Dv) * gz);
            }
        }
    }
}

// ---------------------------------------------------------------------------
extern "C" void kernel_launch(void* const* d_in, const int* in_sizes, int n_in,
                              void* d_out, int out_size)
{
    const float* hidden = (const float*)d_in[0];
    const float* in_w   = (const float*)d_in[1];
    const float* conv_w = (const float*)d_in[2];
    const float* conv_b = (const float*)d_in[3];
    const float* xproj  = (const float*)d_in[4];
    const float* dtw    = (const float*)d_in[5];
    const float* dtb    = (const float*)d_in[6];
    const float* alog   = (const float*)d_in[7];
    const float* Dp     = (const float*)d_in[8];
    const float* outw   = (const float*)d_in[9];
    float* out = (float*)d_out;

    static float  *pxz = nullptr, *px = nullptr, *pxd = nullptr, *pdt = nullptr;
    static __half *pxh = nullptr, *pdtrh = nullptr, *pyh = nullptr,
                  *phid = nullptr, *pinw = nullptr, *pxpw = nullptr,
                  *pdtw = nullptr, *potw = nullptr;
    if (!pxz) {
        cudaGetSymbolAddress((void**)&pxz,   g_xz);
        cudaGetSymbolAddress((void**)&px,    g_x);
        cudaGetSymbolAddress((void**)&pxd,   g_xdbl);
        cudaGetSymbolAddress((void**)&pdt,   g_dt);
        cudaGetSymbolAddress((void**)&pxh,   g_xh);
        cudaGetSymbolAddress((void**)&pdtrh, g_dtrh);
        cudaGetSymbolAddress((void**)&pyh,   g_yh);
        cudaGetSymbolAddress((void**)&phid,  g_hidh);
        cudaGetSymbolAddress((void**)&pinw,  g_inwh);
        cudaGetSymbolAddress((void**)&pxpw,  g_xpwh);
        cudaGetSymbolAddress((void**)&pdtw,  g_dtwh);
        cudaGetSymbolAddress((void**)&potw,  g_otwh);
        cudaFuncSetAttribute(gemm_h,
            cudaFuncAttributePreferredSharedMemoryCarveout, 100);
    }

    // 0) fp32 -> fp16 conversions (weights + hidden)
    f2h_kernel<<<(MROWS * DM + 511) / 512, 512>>>(hidden, phid, MROWS * DM);
    f2h_kernel<<<(2 * DI * DM + 511) / 512, 512>>>(in_w, pinw, 2 * DI * DM);
    f2h_kernel<<<(96 * DI + 511) / 512, 512>>>(xproj, pxpw, 96 * DI);
    f2h_kernel<<<(DI * DR + 511) / 512, 512>>>(dtw, pdtw, DI * DR);
    f2h_kernel<<<(DM * DI + 511) / 512, 512>>>(outw, potw, DM * DI);

    // 1) xz = hidden @ in_proj_w^T          (2048 x 4096 x 1024)
    gemm_h<<<dim3(2 * DI / 64, MROWS / 64, 1), 128>>>(
        phid, DM, pinw, DM, pxz, 2 * DI, 2 * DI, DM, nullptr, 0, 0);

    // 2) x = silu(conv1d(x) + b)  -> fp32 + half
    conv_silu_kernel<<<(MROWS * DI) / 256, 256>>>(pxz, conv_w, conv_b, px, pxh);

    // 3) x_dbl = x @ x_proj_w^T             (2048 x 96 x 2048), split-K=4
    zero_kernel<<<(MROWS * 96 + 511) / 512, 512>>>(pxd, MROWS * 96);
    gemm_h<<<dim3(2, MROWS / 64, 4), 128>>>(
        pxh, DI, pxpw, DI, pxd, 96, 96, DI / 4, nullptr, 0, 1);

    // 3b) dt_r slice -> half
    dtr2h_kernel<<<(MROWS * DR + 511) / 512, 512>>>(pxd, pdtrh);

    // 4) dt = softplus(dt_r @ dt_proj_w^T + b)   (2048 x 2048 x 64)
    gemm_h<<<dim3(DI / 64, MROWS / 64, 1), 128>>>(
        pdtrh, DR, pdtw, DR, pdt, DI, DI, DR, dtb, 1, 0);

    // 5) selective scan -> y half (includes + x*D and *silu(z))
    scan_kernel<<<BSZ * (DI / 16), 256>>>(pdt, px, pxd, alog, Dp, pxz, pyh);

    // 6) out = y @ out_proj_w^T             (2048 x 1024 x 2048)
    gemm_h<<<dim3(DM / 64, MROWS / 64, 1), 128>>>(
        pyh, DI, potw, DI, out, DM, DM, DI, nullptr, 0, 0);
}

// round 7
// speedup vs baseline: 1.1443x; 1.0804x over previous
#include <cuda_runtime.h>
#include <cuda_fp16.h>
#include <cstdint>

// Problem dims (fixed by the reference)
#define BSZ   2
#define LEN   1024
#define DM    1024
#define DI    2048
#define DS    16
#define DR    64
#define MROWS (BSZ*LEN)     // 2048

// ---------------------------------------------------------------------------
// Scratch (allocation-free: __device__ globals)
// ---------------------------------------------------------------------------
__device__ float  g_xz   [MROWS * 2 * DI];  // in_proj out (x | z), fp32
__device__ float  g_x    [MROWS * DI];      // conv+silu out fp32 (scan)
__device__ __half g_xh   [MROWS * DI];      // conv+silu out half (x_proj A)
__device__ float  g_xdbl [MROWS * 96];      // x_proj out (dt_r | B | C) fp32
__device__ __half g_dtrh [MROWS * DR];      // x_dbl[:, :64] half (dt_proj A)
__device__ float  g_dt   [MROWS * DI];      // softplus dt fp32
__device__ __half g_yh   [MROWS * DI];      // gated scan out half (out_proj A)

__device__ __half g_hidh [MROWS * DM];      // hidden in half
__device__ __half g_inwh [2 * DI * DM];     // in_proj_w half
__device__ __half g_xpwh [96 * DI];         // x_proj_w half
__device__ __half g_dtwh [DI * DR];         // dt_proj_w half
__device__ __half g_otwh [DM * DI];         // out_proj_w half

__device__ __forceinline__ void cpa16(void* dst, const void* src, int sz) {
    uint32_t d = (uint32_t)__cvta_generic_to_shared(dst);
    asm volatile("cp.async.cg.shared.global [%0], [%1], 16, %2;\n"
                 :: "r"(d), "l"(src), "r"(sz) : "memory");
}

__device__ __forceinline__ void ldmx4(uint32_t& r0, uint32_t& r1,
                                      uint32_t& r2, uint32_t& r3,
                                      const void* p) {
    uint32_t a = (uint32_t)__cvta_generic_to_shared(p);
    asm volatile("ldmatrix.sync.aligned.m8n8.x4.shared.b16 {%0,%1,%2,%3}, [%4];"
                 : "=r"(r0), "=r"(r1), "=r"(r2), "=r"(r3) : "r"(a));
}

// ---------------------------------------------------------------------------
// fp16 GEMM v6: C[M,N] (+)= A[M,Kslice] * W[N,Kslice]^T, fp32 acc.
// Block tile 128x64, 256 threads = 8 warps (4m x 2n), warp tile 32x32.
// ldmatrix.x4 fragment loads, 24-half padded stride (conflict-free),
// NS=3 cp.async pipeline (27KB smem -> 3 CTAs/SM).
// grid.z splits K; atomic=1 -> atomicAdd; act==1 -> softplus(+bias).
// M%128==0, ksplit%16==0, nstage>=NS-1 (true at all call sites).
// ---------------------------------------------------------------------------
#define NS 3
__global__ void __launch_bounds__(256, 3) gemm_h(
    const __half* __restrict__ A, int lda,
    const __half* __restrict__ W, int ldw,
    float* __restrict__ C, int ldc,
    int N, int ksplit,
    const float* __restrict__ bias, int act, int atomic)
{
    __shared__ __half As[NS][128][24];  // 18KB
    __shared__ __half Ws[NS][64][24];   //  9KB

    const int bm   = blockIdx.y * 128;
    const int bn   = blockIdx.x * 64;
    const int kb   = blockIdx.z * ksplit;
    const int tid  = threadIdx.x;
    const int warp = tid >> 5;
    const int lane = tid & 31;
    const int wm   = (warp & 3) * 32;
    const int wn   = (warp >> 2) * 32;
    const int g    = lane >> 2;   // 0..7
    const int tg   = lane & 3;    // 0..3

    // loaders: A 128 rows x 2 chunks (256 slots), B 64 x 2 (128 slots)
    const int ar  = tid >> 1;            // 0..127
    const int ac  = (tid & 1) * 8;       // halfs
    const __half* ap = &A[(bm + ar) * lda + kb + ac];
    const int br  = (tid & 127) >> 1;    // 0..63
    const int bc  = (tid & 1) * 8;
    const int bsz = (tid < 128 && bn + br < N) ? 16 : 0;
    const __half* wp = &W[(bn + br) * ldw + kb + bc];

    // ldmatrix source offsets
    const int amrow = wm + (lane & 15);
    const int akoff = (lane >> 4) * 8;
    const int bnrow = wn + (lane & 7) + ((lane >> 4) << 3);
    const int bkoff = ((lane >> 3) & 1) * 8;

    float acc[2][4][4];
#pragma unroll
    for (int i = 0; i < 2; i++)
#pragma unroll
        for (int j = 0; j < 4; j++)
#pragma unroll
            for (int c = 0; c < 4; c++) acc[i][j][c] = 0.f;

    const int nstage = ksplit >> 4;

#pragma unroll
    for (int s = 0; s < NS - 1; s++) {
        cpa16(&As[s][ar][ac], ap + s * 16, 16);
        if (tid < 128) cpa16(&Ws[s][br][bc], wp + s * 16, bsz);
        asm volatile("cp.async.commit_group;\n" ::: "memory");
    }

    for (int s = 0; s < nstage; s++) {
        const int buf = s % NS;
        if (s + NS - 1 < nstage) {
            const int nb = (s + NS - 1) % NS;
            const int ko = (s + NS - 1) * 16;
            cpa16(&As[nb][ar][ac], ap + ko, 16);
            if (tid < 128) cpa16(&Ws[nb][br][bc], wp + ko, bsz);
        }
        asm volatile("cp.async.commit_group;\n" ::: "memory");
        asm volatile("cp.async.wait_group %0;\n" :: "n"(NS - 1) : "memory");
        __syncthreads();

        uint32_t a0[4], a1[4], b[8];
        ldmx4(a0[0], a0[1], a0[2], a0[3], &As[buf][amrow][akoff]);
        ldmx4(a1[0], a1[1], a1[2], a1[3], &As[buf][amrow + 16][akoff]);
        ldmx4(b[0], b[1], b[2], b[3], &Ws[buf][bnrow][bkoff]);
        ldmx4(b[4], b[5], b[6], b[7], &Ws[buf][bnrow + 16][bkoff]);

#pragma unroll
        for (int jf = 0; jf < 4; jf++) {
            asm volatile(
                "mma.sync.aligned.m16n8k16.row.col.f32.f16.f16.f32 "
                "{%0,%1,%2,%3},{%4,%5,%6,%7},{%8,%9},{%0,%1,%2,%3};"
                : "+f"(acc[0][jf][0]), "+f"(acc[0][jf][1]),
                  "+f"(acc[0][jf][2]), "+f"(acc[0][jf][3])
                : "r"(a0[0]), "r"(a0[1]), "r"(a0[2]), "r"(a0[3]),
                  "r"(b[2 * jf]), "r"(b[2 * jf + 1]));
            asm volatile(
                "mma.sync.aligned.m16n8k16.row.col.f32.f16.f16.f32 "
                "{%0,%1,%2,%3},{%4,%5,%6,%7},{%8,%9},{%0,%1,%2,%3};"
                : "+f"(acc[1][jf][0]), "+f"(acc[1][jf][1]),
                  "+f"(acc[1][jf][2]), "+f"(acc[1][jf][3])
                : "r"(a1[0]), "r"(a1[1]), "r"(a1[2]), "r"(a1[3]),
                  "r"(b[2 * jf]), "r"(b[2 * jf + 1]));
        }
        __syncthreads();
    }

    // ---- epilogue
#pragma unroll
    for (int mf = 0; mf < 2; mf++)
#pragma unroll
        for (int jf = 0; jf < 4; jf++) {
            const int nn = bn + wn + jf * 8 + tg * 2;
            if (nn < N) {
                const int m0 = bm + wm + mf * 16 + g;
                float v0 = acc[mf][jf][0], v1 = acc[mf][jf][1];
                float v2 = acc[mf][jf][2], v3 = acc[mf][jf][3];
                if (act) {
                    const float b0 = bias[nn], b1 = bias[nn + 1];
                    v0 += b0; v1 += b1; v2 += b0; v3 += b1;
                    v0 = (v0 > 20.f) ? v0 : log1pf(__expf(v0));
                    v1 = (v1 > 20.f) ? v1 : log1pf(__expf(v1));
                    v2 = (v2 > 20.f) ? v2 : log1pf(__expf(v2));
                    v3 = (v3 > 20.f) ? v3 : log1pf(__expf(v3));
                }
                if (atomic) {
                    atomicAdd(&C[m0 * ldc + nn],           v0);
                    atomicAdd(&C[m0 * ldc + nn + 1],       v1);
                    atomicAdd(&C[(m0 + 8) * ldc + nn],     v2);
                    atomicAdd(&C[(m0 + 8) * ldc + nn + 1], v3);
                } else {
                    *(float2*)&C[m0 * ldc + nn]       = make_float2(v0, v1);
                    *(float2*)&C[(m0 + 8) * ldc + nn] = make_float2(v2, v3);
                }
            }
        }
}

// ---------------------------------------------------------------------------
// One fused fp32->fp16 conversion over all 5 tensors (float4 -> 4 halfs).
// ---------------------------------------------------------------------------
#define CS0 (MROWS * DM)        // hidden
#define CS1 (2 * DI * DM)       // in_w
#define CS2 (96 * DI)           // x_proj_w
#define CS3 (DI * DR)           // dt_proj_w
#define CS4 (DM * DI)           // out_proj_w
#define CTOT ((CS0 + CS1 + CS2 + CS3 + CS4) / 4)

__global__ void convert_all(const float* __restrict__ hid,
                            const float* __restrict__ inw,
                            const float* __restrict__ xpw,
                            const float* __restrict__ dtw,
                            const float* __restrict__ otw)
{
    int t = blockIdx.x * 512 + threadIdx.x;
    if (t >= CTOT) return;
    int i = t * 4;
    const float* src; __half* dst; int off;
    if (i < CS0) {
        src = hid; dst = g_hidh; off = i;
    } else if ((i -= CS0) < CS1) {
        src = inw; dst = g_inwh; off = i;
    } else if ((i -= CS1) < CS2) {
        src = xpw; dst = g_xpwh; off = i;
    } else if ((i -= CS2) < CS3) {
        src = dtw; dst = g_dtwh; off = i;
    } else {
        src = otw; dst = g_otwh; off = i - CS3;
    }
    float4 v = *(const float4*)(src + off);
    __half2 h0 = __floats2half2_rn(v.x, v.y);
    __half2 h1 = __floats2half2_rn(v.z, v.w);
    *(__half2*)(dst + off)     = h0;
    *(__half2*)(dst + off + 2) = h1;
}

__global__ void dtr2h_kernel(const float* __restrict__ xdbl, __half* __restrict__ d)
{
    int i = blockIdx.x * 512 + threadIdx.x;   // over MROWS*DR
    if (i < MROWS * DR) {
        int r = i >> 6, c = i & 63;
        d[i] = __float2half_rn(xdbl[r * 96 + c]);
    }
}

__global__ void zero_kernel(float* __restrict__ p, int n)
{
    int i = blockIdx.x * 512 + threadIdx.x;
    if (i < n) p[i] = 0.f;
}

// ---------------------------------------------------------------------------
// Depthwise causal conv (K=4) + bias + SiLU. Writes fp32 (scan) + half (GEMM).
// ---------------------------------------------------------------------------
__global__ void conv_silu_kernel(const float* __restrict__ xz,
                                 const float* __restrict__ w,
                                 const float* __restrict__ bias,
                                 float* __restrict__ xout,
                                 __half* __restrict__ xhout)
{
    int idx = blockIdx.x * blockDim.x + threadIdx.x;   // over MROWS*DI
    int d  = idx & (DI - 1);
    int bl = idx >> 11;                                // (b*L + l)
    int l  = bl & (LEN - 1);
    float accv = bias[d];
#pragma unroll
    for (int k = 0; k < 4; k++) {
        int ll = l + k - 3;
        if (ll >= 0)
            accv += xz[(bl + (ll - l)) * (2 * DI) + d] * w[d * 4 + k];
    }
    float v = accv / (1.f + __expf(-accv));
    xout[idx]  = v;
    xhout[idx] = __float2half_rn(v);
}

// ---------------------------------------------------------------------------
// Selective scan + fused gating. Block = 256 threads = 16 d-channels, one b.
// warp: 2 d-channels x 16 states. Chunks of 128 steps staged in smem.
// ---------------------------------------------------------------------------
#define LC 128
__global__ void __launch_bounds__(256) scan_kernel(
    const float* __restrict__ dtp,
    const float* __restrict__ xp,
    const float* __restrict__ xdbl,  // B at col 64, C at col 80
    const float* __restrict__ A_log,
    const float* __restrict__ Dp,
    const float* __restrict__ xz,    // z-gate
    __half* __restrict__ y)
{
    __shared__ float sB[LC][DS];
    __shared__ float sC[LC][DS];
    __shared__ float sdt[LC][16];
    __shared__ float sx[LC][16];

    const int b   = blockIdx.x / (DI / 16);
    const int d0  = (blockIdx.x % (DI / 16)) * 16;
    const int tid = threadIdx.x;
    const int warp = tid >> 5, lane = tid & 31;
    const int sub = lane >> 4, n = lane & 15;
    const int dl  = warp * 2 + sub;
    const int d   = d0 + dl;

    const float a  = -__expf(A_log[d * DS + n]);
    const float Dv = Dp[d];
    float h = 0.f;

    for (int c = 0; c < LEN / LC; c++) {
        __syncthreads();
        for (int e = tid; e < LC * DS; e += 256) {
            int t = e >> 4, nn = e & 15;
            const float* row = &xdbl[(b * LEN + c * LC + t) * 96];
            sB[t][nn] = row[64 + nn];
            sC[t][nn] = row[80 + nn];
        }
        for (int e = tid; e < LC * 16; e += 256) {
            int t = e >> 4, dd = e & 15;
            int gi = (b * LEN + c * LC + t) * DI + d0 + dd;
            sdt[t][dd] = dtp[gi];
            sx[t][dd]  = xp[gi];
        }
        __syncthreads();

        for (int t = 0; t < LC; t++) {
            float dt = sdt[t][dl];
            float xv = sx[t][dl];
            float dA = __expf(dt * a);
            h = fmaf(dA, h, dt * sB[t][n] * xv);
            float part = h * sC[t][n];
            part += __shfl_xor_sync(0xffffffffu, part, 8);
            part += __shfl_xor_sync(0xffffffffu, part, 4);
            part += __shfl_xor_sync(0xffffffffu, part, 2);
            part += __shfl_xor_sync(0xffffffffu, part, 1);
            if (n == 0) {
                int bl = b * LEN + c * LC + t;
                float z = xz[bl * (2 * DI) + DI + d];
                float gz = z / (1.f + __expf(-z));
                y[bl * DI + d] = __float2half_rn((part + xv * Dv) * gz);
            }
        }
    }
}

// ---------------------------------------------------------------------------
extern "C" void kernel_launch(void* const* d_in, const int* in_sizes, int n_in,
                              void* d_out, int out_size)
{
    const float* hidden = (const float*)d_in[0];
    const float* in_w   = (const float*)d_in[1];
    const float* conv_w = (const float*)d_in[2];
    const float* conv_b = (const float*)d_in[3];
    const float* xproj  = (const float*)d_in[4];
    const float* dtw    = (const float*)d_in[5];
    const float* dtb    = (const float*)d_in[6];
    const float* alog   = (const float*)d_in[7];
    const float* Dp     = (const float*)d_in[8];
    const float* outw   = (const float*)d_in[9];
    float* out = (float*)d_out;

    static float  *pxz = nullptr, *px = nullptr, *pxd = nullptr, *pdt = nullptr;
    static __half *pxh = nullptr, *pdtrh = nullptr, *pyh = nullptr,
                  *phid = nullptr, *pinw = nullptr, *pxpw = nullptr,
                  *pdtw = nullptr, *potw = nullptr;
    if (!pxz) {
        cudaGetSymbolAddress((void**)&pxz,   g_xz);
        cudaGetSymbolAddress((void**)&px,    g_x);
        cudaGetSymbolAddress((void**)&pxd,   g_xdbl);
        cudaGetSymbolAddress((void**)&pdt,   g_dt);
        cudaGetSymbolAddress((void**)&pxh,   g_xh);
        cudaGetSymbolAddress((void**)&pdtrh, g_dtrh);
        cudaGetSymbolAddress((void**)&pyh,   g_yh);
        cudaGetSymbolAddress((void**)&phid,  g_hidh);
        cudaGetSymbolAddress((void**)&pinw,  g_inwh);
        cudaGetSymbolAddress((void**)&pxpw,  g_xpwh);
        cudaGetSymbolAddress((void**)&pdtw,  g_dtwh);
        cudaGetSymbolAddress((void**)&potw,  g_otwh);
        cudaFuncSetAttribute(gemm_h,
            cudaFuncAttributePreferredSharedMemoryCarveout, 100);
    }

    // 0) fp32 -> fp16 (all tensors, one kernel)
    convert_all<<<(CTOT + 511) / 512, 512>>>(hidden, in_w, xproj, dtw, outw);

    // 1) xz = hidden @ in_proj_w^T          (2048 x 4096 x 1024)
    gemm_h<<<dim3(2 * DI / 64, MROWS / 128, 1), 256>>>(
        phid, DM, pinw, DM, pxz, 2 * DI, 2 * DI, DM, nullptr, 0, 0);

    // 2) x = silu(conv1d(x) + b)  -> fp32 + half
    conv_silu_kernel<<<(MROWS * DI) / 256, 256>>>(pxz, conv_w, conv_b, px, pxh);

    // 3) x_dbl = x @ x_proj_w^T             (2048 x 96 x 2048), split-K=4
    zero_kernel<<<(MROWS * 96 + 511) / 512, 512>>>(pxd, MROWS * 96);
    gemm_h<<<dim3(2, MROWS / 128, 4), 256>>>(
        pxh, DI, pxpw, DI, pxd, 96, 96, DI / 4, nullptr, 0, 1);

    // 3b) dt_r slice -> half
    dtr2h_kernel<<<(MROWS * DR + 511) / 512, 512>>>(pxd, pdtrh);

    // 4) dt = softplus(dt_r @ dt_proj_w^T + b)   (2048 x 2048 x 64)
    gemm_h<<<dim3(DI / 64, MROWS / 128, 1), 256>>>(
        pdtrh, DR, pdtw, DR, pdt, DI, DI, DR, dtb, 1, 0);

    // 5) selective scan -> y half (includes + x*D and *silu(z))
    scan_kernel<<<BSZ * (DI / 16), 256>>>(pdt, px, pxd, alog, Dp, pxz, pyh);

    // 6) out = y @ out_proj_w^T             (2048 x 1024 x 2048)
    gemm_h<<<dim3(DM / 64, MROWS / 128, 1), 256>>>(
        pyh, DI, potw, DI, out, DM, DM, DI, nullptr, 0, 0);
}

// round 9
// speedup vs baseline: 1.2109x; 1.0582x over previous
#include <cuda_runtime.h>
#include <cuda_fp16.h>
#include <cstdint>

// Problem dims (fixed by the reference)
#define BSZ   2
#define LEN   1024
#define DM    1024
#define DI    2048
#define DS    16
#define DR    64
#define MROWS (BSZ*LEN)     // 2048

// ---------------------------------------------------------------------------
// Scratch (allocation-free: __device__ globals)
// ---------------------------------------------------------------------------
__device__ float  g_xz   [MROWS * 2 * DI];  // in_proj out (x | z), fp32
__device__ float  g_x    [MROWS * DI];      // conv+silu out fp32 (scan)
__device__ __half g_xh   [MROWS * DI];      // conv+silu out half (x_proj A)
__device__ float  g_xdbl [MROWS * 96];      // x_proj out (dt_r | B | C) fp32
__device__ __half g_dtrh [MROWS * DR];      // x_dbl[:, :64] half (dt_proj A)
__device__ float  g_dt   [MROWS * DI];      // softplus dt fp32
__device__ __half g_yh   [MROWS * DI];      // gated scan out half (out_proj A)

__device__ __half g_hidh [MROWS * DM];      // hidden in half
__device__ __half g_inwh [2 * DI * DM];     // in_proj_w half
__device__ __half g_xpwh [96 * DI];         // x_proj_w half
__device__ __half g_dtwh [DI * DR];         // dt_proj_w half
__device__ __half g_otwh [DM * DI];         // out_proj_w half

__device__ __forceinline__ void cpa16(void* dst, const void* src, int sz) {
    uint32_t d = (uint32_t)__cvta_generic_to_shared(dst);
    asm volatile("cp.async.cg.shared.global [%0], [%1], 16, %2;\n"
                 :: "r"(d), "l"(src), "r"(sz) : "memory");
}

__device__ __forceinline__ void ldmx4(uint32_t& r0, uint32_t& r1,
                                      uint32_t& r2, uint32_t& r3,
                                      const void* p) {
    uint32_t a = (uint32_t)__cvta_generic_to_shared(p);
    asm volatile("ldmatrix.sync.aligned.m8n8.x4.shared.b16 {%0,%1,%2,%3}, [%4];"
                 : "=r"(r0), "=r"(r1), "=r"(r2), "=r"(r3) : "r"(a));
}

// ---------------------------------------------------------------------------
// fp16 GEMM v8: C[M,N] (+)= A[M,Kslice] * W[N,Kslice]^T, fp32 acc.
// CTA tile 128x128, 256 threads = 8 warps (2m x 4n), warp tile 64x32.
// K stage = 32 halfs; NS=3 cp.async pipeline; pad-40 smem rows
// (conflict-free for both cp.async stores and ldmatrix reads).
// 32 HMMA per warp between consecutive __syncthreads.
// grid.z splits K; atomic=1 -> atomicAdd; act==1 -> softplus(+bias).
// M%128==0, ksplit%32==0 required (true at all call sites).
// ---------------------------------------------------------------------------
#define BK 32
#define NS 3
#define SSTR 40                    // halfs per smem row
#define ABUF (128 * SSTR)          // halfs per stage per matrix
#define SMEM_BYTES (2 * NS * ABUF * 2)

__global__ void __launch_bounds__(256, 2) gemm_h(
    const __half* __restrict__ A, int lda,
    const __half* __restrict__ W, int ldw,
    float* __restrict__ C, int ldc,
    int N, int ksplit,
    const float* __restrict__ bias, int act, int atomic)
{
    extern __shared__ __half sm[];
    __half* Asm = sm;              // [NS][128][SSTR]
    __half* Wsm = sm + NS * ABUF;

    const int bm   = blockIdx.y * 128;
    const int bn   = blockIdx.x * 128;
    const int kb   = blockIdx.z * ksplit;
    const int tid  = threadIdx.x;
    const int warp = tid >> 5;
    const int lane = tid & 31;
    const int wm   = (warp & 1) * 64;
    const int wn   = (warp >> 1) * 32;
    const int g    = lane >> 2;
    const int tg   = lane & 3;

    // loader: row lr, two 16B chunks at halves lc and lc+8
    const int lr = tid >> 1;               // 0..127
    const int lc = (tid & 1) * 16;         // 0 or 16 (halfs)
    const bool wrow_ok = (bn + lr < N);
    const __half* ap = &A[(bm + lr) * lda + kb + lc];
    const __half* wp = &W[(bn + lr) * ldw + kb + lc];
    __half* asd = &Asm[lr * SSTR + lc];
    __half* wsd = &Wsm[lr * SSTR + lc];

    // ldmatrix addresses (pattern validated in round 7)
    const int arow = wm + (lane & 15);
    const int akof = (lane >> 4) * 8;
    const int brow = wn + (lane & 7) + ((lane >> 4) << 3);
    const int bkof = ((lane >> 3) & 1) * 8;

    float acc[4][4][4];
#pragma unroll
    for (int i = 0; i < 4; i++)
#pragma unroll
        for (int j = 0; j < 4; j++)
#pragma unroll
            for (int c = 0; c < 4; c++) acc[i][j][c] = 0.f;

    const int nstage = ksplit / BK;

    // prologue: stages 0..NS-2
#pragma unroll
    for (int s = 0; s < NS - 1; s++) {
        const int ks  = s * BK;
        const int vz  = (s < nstage) ? 16 : 0;
        const int vzw = (vz && wrow_ok) ? 16 : 0;
        cpa16(asd + (size_t)s * ABUF,     ap + ks,     vz);
        cpa16(asd + (size_t)s * ABUF + 8, ap + ks + 8, vz);
        cpa16(wsd + (size_t)s * ABUF,     wp + ks,     vzw);
        cpa16(wsd + (size_t)s * ABUF + 8, wp + ks + 8, vzw);
        asm volatile("cp.async.commit_group;" ::: "memory");
    }

    for (int s = 0; s < nstage; s++) {
        const int buf = s % NS;
        asm volatile("cp.async.wait_group %0;" :: "n"(NS - 2) : "memory");
        __syncthreads();

        // prefetch stage s+NS-1 into buffer (s-1)%NS (its readers are done)
        {
            const int sp  = s + NS - 1;
            const int pb  = sp % NS;
            const int ks  = sp * BK;
            const int vz  = (sp < nstage) ? 16 : 0;
            const int vzw = (vz && wrow_ok) ? 16 : 0;
            cpa16(asd + (size_t)pb * ABUF,     ap + ks,     vz);
            cpa16(asd + (size_t)pb * ABUF + 8, ap + ks + 8, vz);
            cpa16(wsd + (size_t)pb * ABUF,     wp + ks,     vzw);
            cpa16(wsd + (size_t)pb * ABUF + 8, wp + ks + 8, vzw);
            asm volatile("cp.async.commit_group;" ::: "memory");
        }

        const __half* ab = Asm + (size_t)buf * ABUF;
        const __half* wb = Wsm + (size_t)buf * ABUF;
#pragma unroll
        for (int kk = 0; kk < BK; kk += 16) {
            uint32_t a[4][4], b[8];
#pragma unroll
            for (int mi = 0; mi < 4; mi++)
                ldmx4(a[mi][0], a[mi][1], a[mi][2], a[mi][3],
                      ab + (arow + 16 * mi) * SSTR + kk + akof);
            ldmx4(b[0], b[1], b[2], b[3],
                  wb + brow * SSTR + kk + bkof);
            ldmx4(b[4], b[5], b[6], b[7],
                  wb + (brow + 16) * SSTR + kk + bkof);
#pragma unroll
            for (int mi = 0; mi < 4; mi++)
#pragma unroll
                for (int jf = 0; jf < 4; jf++)
                    asm volatile(
                        "mma.sync.aligned.m16n8k16.row.col.f32.f16.f16.f32 "
                        "{%0,%1,%2,%3},{%4,%5,%6,%7},{%8,%9},{%0,%1,%2,%3};"
                        : "+f"(acc[mi][jf][0]), "+f"(acc[mi][jf][1]),
                          "+f"(acc[mi][jf][2]), "+f"(acc[mi][jf][3])
                        : "r"(a[mi][0]), "r"(a[mi][1]),
                          "r"(a[mi][2]), "r"(a[mi][3]),
                          "r"(b[2 * jf]), "r"(b[2 * jf + 1]));
        }
    }

    // ---- epilogue
#pragma unroll
    for (int mi = 0; mi < 4; mi++)
#pragma unroll
        for (int jf = 0; jf < 4; jf++) {
            const int nn = bn + wn + jf * 8 + tg * 2;
            if (nn < N) {
                const int m0 = bm + wm + mi * 16 + g;
                float v0 = acc[mi][jf][0], v1 = acc[mi][jf][1];
                float v2 = acc[mi][jf][2], v3 = acc[mi][jf][3];
                if (act) {
                    const float b0 = bias[nn], b1 = bias[nn + 1];
                    v0 += b0; v1 += b1; v2 += b0; v3 += b1;
                    v0 = (v0 > 20.f) ? v0 : log1pf(__expf(v0));
                    v1 = (v1 > 20.f) ? v1 : log1pf(__expf(v1));
                    v2 = (v2 > 20.f) ? v2 : log1pf(__expf(v2));
                    v3 = (v3 > 20.f) ? v3 : log1pf(__expf(v3));
                }
                if (atomic) {
                    atomicAdd(&C[m0 * ldc + nn],           v0);
                    atomicAdd(&C[m0 * ldc + nn + 1],       v1);
                    atomicAdd(&C[(m0 + 8) * ldc + nn],     v2);
                    atomicAdd(&C[(m0 + 8) * ldc + nn + 1], v3);
                } else {
                    *(float2*)&C[m0 * ldc + nn]       = make_float2(v0, v1);
                    *(float2*)&C[(m0 + 8) * ldc + nn] = make_float2(v2, v3);
                }
            }
        }
}

// ---------------------------------------------------------------------------
// fp32 -> fp16 conversions (weights kernel + hidden kernel)
// ---------------------------------------------------------------------------
#define CS0 (MROWS * DM)
#define CS1 (2 * DI * DM)
#define CS2 (96 * DI)
#define CS3 (DI * DR)
#define CS4 (DM * DI)
#define CWT ((CS1 + CS2 + CS3 + CS4) / 4)

__global__ void convert_w(const float* __restrict__ inw,
                          const float* __restrict__ xpw,
                          const float* __restrict__ dtw,
                          const float* __restrict__ otw)
{
    int t = blockIdx.x * 512 + threadIdx.x;
    if (t >= CWT) return;
    int i = t * 4;
    const float* src; __half* dst; int off;
    if (i < CS1) {
        src = inw; dst = g_inwh; off = i;
    } else if ((i -= CS1) < CS2) {
        src = xpw; dst = g_xpwh; off = i;
    } else if ((i -= CS2) < CS3) {
        src = dtw; dst = g_dtwh; off = i;
    } else {
        src = otw; dst = g_otwh; off = i - CS3;
    }
    float4 v = *(const float4*)(src + off);
    *(__half2*)(dst + off)     = __floats2half2_rn(v.x, v.y);
    *(__half2*)(dst + off + 2) = __floats2half2_rn(v.z, v.w);
}

__global__ void convert_hid(const float* __restrict__ hid)
{
    int t = blockIdx.x * 512 + threadIdx.x;
    if (t >= CS0 / 4) return;
    int off = t * 4;
    float4 v = *(const float4*)(hid + off);
    *(__half2*)(g_hidh + off)     = __floats2half2_rn(v.x, v.y);
    *(__half2*)(g_hidh + off + 2) = __floats2half2_rn(v.z, v.w);
}

__global__ void dtr2h_kernel(const float* __restrict__ xdbl, __half* __restrict__ d)
{
    int i = blockIdx.x * 512 + threadIdx.x;   // over MROWS*DR
    if (i < MROWS * DR) {
        int r = i >> 6, c = i & 63;
        d[i] = __float2half_rn(xdbl[r * 96 + c]);
    }
}

__global__ void zero_kernel(float* __restrict__ p, int n)
{
    int i = blockIdx.x * 512 + threadIdx.x;
    if (i < n) p[i] = 0.f;
}

// ---------------------------------------------------------------------------
// Depthwise causal conv (K=4) + bias + SiLU. Writes fp32 (scan) + half (GEMM).
// ---------------------------------------------------------------------------
__global__ void conv_silu_kernel(const float* __restrict__ xz,
                                 const float* __restrict__ w,
                                 const float* __restrict__ bias,
                                 float* __restrict__ xout,
                                 __half* __restrict__ xhout)
{
    int idx = blockIdx.x * blockDim.x + threadIdx.x;   // over MROWS*DI
    int d  = idx & (DI - 1);
    int bl = idx >> 11;                                // (b*L + l)
    int l  = bl & (LEN - 1);
    float accv = bias[d];
#pragma unroll
    for (int k = 0; k < 4; k++) {
        int ll = l + k - 3;
        if (ll >= 0)
            accv += xz[(bl + (ll - l)) * (2 * DI) + d] * w[d * 4 + k];
    }
    float v = accv / (1.f + __expf(-accv));
    xout[idx]  = v;
    xhout[idx] = __float2half_rn(v);
}

// ---------------------------------------------------------------------------
// Selective scan + fused gating. Block = 256 threads = 16 d-channels, one b.
// ---------------------------------------------------------------------------
#define LC 128
__global__ void __launch_bounds__(256) scan_kernel(
    const float* __restrict__ dtp,
    const float* __restrict__ xp,
    const float* __restrict__ xdbl,  // B at col 64, C at col 80
    const float* __restrict__ A_log,
    const float* __restrict__ Dp,
    const float* __restrict__ xz,    // z-gate
    __half* __restrict__ y)
{
    __shared__ float sB[LC][DS];
    __shared__ float sC[LC][DS];
    __shared__ float sdt[LC][16];
    __shared__ float sx[LC][16];

    const int b   = blockIdx.x / (DI / 16);
    const int d0  = (blockIdx.x % (DI / 16)) * 16;
    const int tid = threadIdx.x;
    const int warp = tid >> 5, lane = tid & 31;
    const int sub = lane >> 4, n = lane & 15;
    const int dl  = warp * 2 + sub;
    const int d   = d0 + dl;

    const float a  = -__expf(A_log[d * DS + n]);
    const float Dv = Dp[d];
    float h = 0.f;

    for (int c = 0; c < LEN / LC; c++) {
        __syncthreads();
        for (int e = tid; e < LC * DS; e += 256) {
            int t = e >> 4, nn = e & 15;
            const float* row = &xdbl[(b * LEN + c * LC + t) * 96];
            sB[t][nn] = row[64 + nn];
            sC[t][nn] = row[80 + nn];
        }
        for (int e = tid; e < LC * 16; e += 256) {
            int t = e >> 4, dd = e & 15;
            int gi = (b * LEN + c * LC + t) * DI + d0 + dd;
            sdt[t][dd] = dtp[gi];
            sx[t][dd]  = xp[gi];
        }
        __syncthreads();

        for (int t = 0; t < LC; t++) {
            float dt = sdt[t][dl];
            float xv = sx[t][dl];
            float dA = __expf(dt * a);
            h = fmaf(dA, h, dt * sB[t][n] * xv);
            float part = h * sC[t][n];
            part += __shfl_xor_sync(0xffffffffu, part, 8);
            part += __shfl_xor_sync(0xffffffffu, part, 4);
            part += __shfl_xor_sync(0xffffffffu, part, 2);
            part += __shfl_xor_sync(0xffffffffu, part, 1);
            if (n == 0) {
                int bl = b * LEN + c * LC + t;
                float z = xz[bl * (2 * DI) + DI + d];
                float gz = z / (1.f + __expf(-z));
                y[bl * DI + d] = __float2half_rn((part + xv * Dv) * gz);
            }
        }
    }
}

// ---------------------------------------------------------------------------
extern "C" void kernel_launch(void* const* d_in, const int* in_sizes, int n_in,
                              void* d_out, int out_size)
{
    const float* hidden = (const float*)d_in[0];
    const float* in_w   = (const float*)d_in[1];
    const float* conv_w = (const float*)d_in[2];
    const float* conv_b = (const float*)d_in[3];
    const float* xproj  = (const float*)d_in[4];
    const float* dtw    = (const float*)d_in[5];
    const float* dtb    = (const float*)d_in[6];
    const float* alog   = (const float*)d_in[7];
    const float* Dp     = (const float*)d_in[8];
    const float* outw   = (const float*)d_in[9];
    float* out = (float*)d_out;

    static float  *pxz = nullptr, *px = nullptr, *pxd = nullptr, *pdt = nullptr;
    static __half *pxh = nullptr, *pdtrh = nullptr, *pyh = nullptr,
                  *phid = nullptr, *pinw = nullptr, *pxpw = nullptr,
                  *pdtw = nullptr, *potw = nullptr;
    if (!pxz) {
        cudaGetSymbolAddress((void**)&pxz,   g_xz);
        cudaGetSymbolAddress((void**)&px,    g_x);
        cudaGetSymbolAddress((void**)&pxd,   g_xdbl);
        cudaGetSymbolAddress((void**)&pdt,   g_dt);
        cudaGetSymbolAddress((void**)&pxh,   g_xh);
        cudaGetSymbolAddress((void**)&pdtrh, g_dtrh);
        cudaGetSymbolAddress((void**)&pyh,   g_yh);
        cudaGetSymbolAddress((void**)&phid,  g_hidh);
        cudaGetSymbolAddress((void**)&pinw,  g_inwh);
        cudaGetSymbolAddress((void**)&pxpw,  g_xpwh);
        cudaGetSymbolAddress((void**)&pdtw,  g_dtwh);
        cudaGetSymbolAddress((void**)&potw,  g_otwh);
        cudaFuncSetAttribute(gemm_h,
            cudaFuncAttributeMaxDynamicSharedMemorySize, SMEM_BYTES);
    }

    // #1 weights -> fp16
    convert_w<<<(CWT + 511) / 512, 512>>>(in_w, xproj, dtw, outw);
    // #2 hidden -> fp16
    convert_hid<<<(CS0 / 4 + 511) / 512, 512>>>(hidden);
    // #3 zero split-K accumulator
    zero_kernel<<<(MROWS * 96 + 511) / 512, 512>>>(pxd, MROWS * 96);

    // #4 xz = hidden @ in_proj_w^T          (2048 x 4096 x 1024)  [profiled]
    gemm_h<<<dim3(2 * DI / 128, MROWS / 128, 1), 256, SMEM_BYTES>>>(
        phid, DM, pinw, DM, pxz, 2 * DI, 2 * DI, DM, nullptr, 0, 0);

    // #5 x = silu(conv1d(x) + b)  -> fp32 + half
    conv_silu_kernel<<<(MROWS * DI) / 256, 256>>>(pxz, conv_w, conv_b, px, pxh);

    // #6 x_dbl = x @ x_proj_w^T             (2048 x 96 x 2048), split-K=8
    gemm_h<<<dim3(1, MROWS / 128, 8), 256, SMEM_BYTES>>>(
        pxh, DI, pxpw, DI, pxd, 96, 96, DI / 8, nullptr, 0, 1);

    // #7 dt_r slice -> half
    dtr2h_kernel<<<(MROWS * DR + 511) / 512, 512>>>(pxd, pdtrh);

    // #8 dt = softplus(dt_r @ dt_proj_w^T + b)   (2048 x 2048 x 64)
    gemm_h<<<dim3(DI / 128, MROWS / 128, 1), 256, SMEM_BYTES>>>(
        pdtrh, DR, pdtw, DR, pdt, DI, DI, DR, dtb, 1, 0);

    // #9 selective scan -> y half (includes + x*D and *silu(z))
    scan_kernel<<<BSZ * (DI / 16), 256>>>(pdt, px, pxd, alog, Dp, pxz, pyh);

    // #10 out = y @ out_proj_w^T            (2048 x 1024 x 2048)
    gemm_h<<<dim3(DM / 128, MROWS / 128, 1), 256, SMEM_BYTES>>>(
        pyh, DI, potw, DI, out, DM, DM, DI, nullptr, 0, 0);
}

// round 10
// speedup vs baseline: 2.2332x; 1.8442x over previous
#include <cuda_runtime.h>
#include <cuda_fp16.h>
#include <cstdint>

// Problem dims (fixed by the reference)
#define BSZ   2
#define LEN   1024
#define DM    1024
#define DI    2048
#define DS    16
#define DR    64
#define MROWS (BSZ*LEN)     // 2048
#define NSEG  8
#define TSEG  (LEN/NSEG)    // 128

// ---------------------------------------------------------------------------
// Scratch (allocation-free: __device__ globals)
// ---------------------------------------------------------------------------
__device__ float  g_xz   [MROWS * 2 * DI];  // in_proj out (x | z), fp32
__device__ float  g_x    [MROWS * DI];      // conv+silu out fp32 (scan)
__device__ __half g_xh   [MROWS * DI];      // conv+silu out half (x_proj A)
__device__ float  g_xdbl [MROWS * 96];      // x_proj out (dt_r | B | C) fp32
__device__ __half g_dtrh [MROWS * DR];      // x_dbl[:, :64] half (dt_proj A)
__device__ float  g_dt   [MROWS * DI];      // softplus dt fp32
__device__ __half g_yh   [MROWS * DI];      // gated scan out half (out_proj A)
__device__ float  g_yloc [MROWS * DI];      // segment-local scan partials
__device__ float  g_P    [BSZ * DI * DS * NSEG];
__device__ float  g_Q    [BSZ * DI * DS * NSEG];
__device__ float  g_hin  [BSZ * DI * DS * NSEG];

__device__ __half g_hidh [MROWS * DM];      // hidden in half
__device__ __half g_inwh [2 * DI * DM];     // in_proj_w half
__device__ __half g_xpwh [96 * DI];         // x_proj_w half
__device__ __half g_dtwh [DI * DR];         // dt_proj_w half
__device__ __half g_otwh [DM * DI];         // out_proj_w half

__device__ __forceinline__ void cpa16(void* dst, const void* src, int sz) {
    uint32_t d = (uint32_t)__cvta_generic_to_shared(dst);
    asm volatile("cp.async.cg.shared.global [%0], [%1], 16, %2;\n"
                 :: "r"(d), "l"(src), "r"(sz) : "memory");
}

__device__ __forceinline__ void ldmx4(uint32_t& r0, uint32_t& r1,
                                      uint32_t& r2, uint32_t& r3,
                                      const void* p) {
    uint32_t a = (uint32_t)__cvta_generic_to_shared(p);
    asm volatile("ldmatrix.sync.aligned.m8n8.x4.shared.b16 {%0,%1,%2,%3}, [%4];"
                 : "=r"(r0), "=r"(r1), "=r"(r2), "=r"(r3) : "r"(a));
}

// ---------------------------------------------------------------------------
// fp16 GEMM v8 (unchanged from round 9): C[M,N] (+)= A*W^T, fp32 acc.
// CTA 128x128, 256 thr, warp tile 64x32, NS=3 cp.async pipeline.
// ---------------------------------------------------------------------------
#define BK 32
#define NS 3
#define SSTR 40
#define ABUF (128 * SSTR)
#define SMEM_BYTES (2 * NS * ABUF * 2)

__global__ void __launch_bounds__(256, 2) gemm_h(
    const __half* __restrict__ A, int lda,
    const __half* __restrict__ W, int ldw,
    float* __restrict__ C, int ldc,
    int N, int ksplit,
    const float* __restrict__ bias, int act, int atomic)
{
    extern __shared__ __half sm[];
    __half* Asm = sm;
    __half* Wsm = sm + NS * ABUF;

    const int bm   = blockIdx.y * 128;
    const int bn   = blockIdx.x * 128;
    const int kb   = blockIdx.z * ksplit;
    const int tid  = threadIdx.x;
    const int warp = tid >> 5;
    const int lane = tid & 31;
    const int wm   = (warp & 1) * 64;
    const int wn   = (warp >> 1) * 32;
    const int g    = lane >> 2;
    const int tg   = lane & 3;

    const int lr = tid >> 1;
    const int lc = (tid & 1) * 16;
    const bool wrow_ok = (bn + lr < N);
    const __half* ap = &A[(bm + lr) * lda + kb + lc];
    const __half* wp = &W[(bn + lr) * ldw + kb + lc];
    __half* asd = &Asm[lr * SSTR + lc];
    __half* wsd = &Wsm[lr * SSTR + lc];

    const int arow = wm + (lane & 15);
    const int akof = (lane >> 4) * 8;
    const int brow = wn + (lane & 7) + ((lane >> 4) << 3);
    const int bkof = ((lane >> 3) & 1) * 8;

    float acc[4][4][4];
#pragma unroll
    for (int i = 0; i < 4; i++)
#pragma unroll
        for (int j = 0; j < 4; j++)
#pragma unroll
            for (int c = 0; c < 4; c++) acc[i][j][c] = 0.f;

    const int nstage = ksplit / BK;

#pragma unroll
    for (int s = 0; s < NS - 1; s++) {
        const int ks  = s * BK;
        const int vz  = (s < nstage) ? 16 : 0;
        const int vzw = (vz && wrow_ok) ? 16 : 0;
        cpa16(asd + (size_t)s * ABUF,     ap + ks,     vz);
        cpa16(asd + (size_t)s * ABUF + 8, ap + ks + 8, vz);
        cpa16(wsd + (size_t)s * ABUF,     wp + ks,     vzw);
        cpa16(wsd + (size_t)s * ABUF + 8, wp + ks + 8, vzw);
        asm volatile("cp.async.commit_group;" ::: "memory");
    }

    for (int s = 0; s < nstage; s++) {
        const int buf = s % NS;
        asm volatile("cp.async.wait_group %0;" :: "n"(NS - 2) : "memory");
        __syncthreads();

        {
            const int sp  = s + NS - 1;
            const int pb  = sp % NS;
            const int ks  = sp * BK;
            const int vz  = (sp < nstage) ? 16 : 0;
            const int vzw = (vz && wrow_ok) ? 16 : 0;
            cpa16(asd + (size_t)pb * ABUF,     ap + ks,     vz);
            cpa16(asd + (size_t)pb * ABUF + 8, ap + ks + 8, vz);
            cpa16(wsd + (size_t)pb * ABUF,     wp + ks,     vzw);
            cpa16(wsd + (size_t)pb * ABUF + 8, wp + ks + 8, vzw);
            asm volatile("cp.async.commit_group;" ::: "memory");
        }

        const __half* ab = Asm + (size_t)buf * ABUF;
        const __half* wb = Wsm + (size_t)buf * ABUF;
#pragma unroll
        for (int kk = 0; kk < BK; kk += 16) {
            uint32_t a[4][4], b[8];
#pragma unroll
            for (int mi = 0; mi < 4; mi++)
                ldmx4(a[mi][0], a[mi][1], a[mi][2], a[mi][3],
                      ab + (arow + 16 * mi) * SSTR + kk + akof);
            ldmx4(b[0], b[1], b[2], b[3],
                  wb + brow * SSTR + kk + bkof);
            ldmx4(b[4], b[5], b[6], b[7],
                  wb + (brow + 16) * SSTR + kk + bkof);
#pragma unroll
            for (int mi = 0; mi < 4; mi++)
#pragma unroll
                for (int jf = 0; jf < 4; jf++)
                    asm volatile(
                        "mma.sync.aligned.m16n8k16.row.col.f32.f16.f16.f32 "
                        "{%0,%1,%2,%3},{%4,%5,%6,%7},{%8,%9},{%0,%1,%2,%3};"
                        : "+f"(acc[mi][jf][0]), "+f"(acc[mi][jf][1]),
                          "+f"(acc[mi][jf][2]), "+f"(acc[mi][jf][3])
                        : "r"(a[mi][0]), "r"(a[mi][1]),
                          "r"(a[mi][2]), "r"(a[mi][3]),
                          "r"(b[2 * jf]), "r"(b[2 * jf + 1]));
        }
    }

#pragma unroll
    for (int mi = 0; mi < 4; mi++)
#pragma unroll
        for (int jf = 0; jf < 4; jf++) {
            const int nn = bn + wn + jf * 8 + tg * 2;
            if (nn < N) {
                const int m0 = bm + wm + mi * 16 + g;
                float v0 = acc[mi][jf][0], v1 = acc[mi][jf][1];
                float v2 = acc[mi][jf][2], v3 = acc[mi][jf][3];
                if (act) {
                    const float b0 = bias[nn], b1 = bias[nn + 1];
                    v0 += b0; v1 += b1; v2 += b0; v3 += b1;
                    v0 = (v0 > 20.f) ? v0 : log1pf(__expf(v0));
                    v1 = (v1 > 20.f) ? v1 : log1pf(__expf(v1));
                    v2 = (v2 > 20.f) ? v2 : log1pf(__expf(v2));
                    v3 = (v3 > 20.f) ? v3 : log1pf(__expf(v3));
                }
                if (atomic) {
                    atomicAdd(&C[m0 * ldc + nn],           v0);
                    atomicAdd(&C[m0 * ldc + nn + 1],       v1);
                    atomicAdd(&C[(m0 + 8) * ldc + nn],     v2);
                    atomicAdd(&C[(m0 + 8) * ldc + nn + 1], v3);
                } else {
                    *(float2*)&C[m0 * ldc + nn]       = make_float2(v0, v1);
                    *(float2*)&C[(m0 + 8) * ldc + nn] = make_float2(v2, v3);
                }
            }
        }
}

// ---------------------------------------------------------------------------
// fp32 -> fp16 conversions
// ---------------------------------------------------------------------------
#define CS0 (MROWS * DM)
#define CS1 (2 * DI * DM)
#define CS2 (96 * DI)
#define CS3 (DI * DR)
#define CS4 (DM * DI)
#define CWT ((CS1 + CS2 + CS3 + CS4) / 4)

__global__ void convert_w(const float* __restrict__ inw,
                          const float* __restrict__ xpw,
                          const float* __restrict__ dtw,
                          const float* __restrict__ otw)
{
    int t = blockIdx.x * 512 + threadIdx.x;
    if (t >= CWT) return;
    int i = t * 4;
    const float* src; __half* dst; int off;
    if (i < CS1) {
        src = inw; dst = g_inwh; off = i;
    } else if ((i -= CS1) < CS2) {
        src = xpw; dst = g_xpwh; off = i;
    } else if ((i -= CS2) < CS3) {
        src = dtw; dst = g_dtwh; off = i;
    } else {
        src = otw; dst = g_otwh; off = i - CS3;
    }
    float4 v = *(const float4*)(src + off);
    *(__half2*)(dst + off)     = __floats2half2_rn(v.x, v.y);
    *(__half2*)(dst + off + 2) = __floats2half2_rn(v.z, v.w);
}

__global__ void convert_hid(const float* __restrict__ hid)
{
    int t = blockIdx.x * 512 + threadIdx.x;
    if (t >= CS0 / 4) return;
    int off = t * 4;
    float4 v = *(const float4*)(hid + off);
    *(__half2*)(g_hidh + off)     = __floats2half2_rn(v.x, v.y);
    *(__half2*)(g_hidh + off + 2) = __floats2half2_rn(v.z, v.w);
}

__global__ void dtr2h_kernel(const float* __restrict__ xdbl, __half* __restrict__ d)
{
    int i = blockIdx.x * 512 + threadIdx.x;
    if (i < MROWS * DR) {
        int r = i >> 6, c = i & 63;
        d[i] = __float2half_rn(xdbl[r * 96 + c]);
    }
}

__global__ void zero_kernel(float* __restrict__ p, int n)
{
    int i = blockIdx.x * 512 + threadIdx.x;
    if (i < n) p[i] = 0.f;
}

// ---------------------------------------------------------------------------
// Depthwise causal conv (K=4) + bias + SiLU.
// ---------------------------------------------------------------------------
__global__ void conv_silu_kernel(const float* __restrict__ xz,
                                 const float* __restrict__ w,
                                 const float* __restrict__ bias,
                                 float* __restrict__ xout,
                                 __half* __restrict__ xhout)
{
    int idx = blockIdx.x * blockDim.x + threadIdx.x;
    int d  = idx & (DI - 1);
    int bl = idx >> 11;
    int l  = bl & (LEN - 1);
    float accv = bias[d];
#pragma unroll
    for (int k = 0; k < 4; k++) {
        int ll = l + k - 3;
        if (ll >= 0)
            accv += xz[(bl + (ll - l)) * (2 * DI) + d] * w[d * 4 + k];
    }
    float v = accv / (1.f + __expf(-accv));
    xout[idx]  = v;
    xhout[idx] = __float2half_rn(v);
}

// ---------------------------------------------------------------------------
// Segmented selective scan.
// Phase A: per-segment local scan (h_in = 0): y_loc, P = prod(dA), Q = h_end.
// Phase B: combine (P,Q) across segments -> h_in per (b,d,n,seg).
// Phase C: corrections + x*D + silu(z) gate -> half output.
// Block = 256 thr = 16 d-channels of one (b, seg). Warp: 2d x 16n.
// ---------------------------------------------------------------------------
__global__ void __launch_bounds__(256) scanA(
    const float* __restrict__ dtp,
    const float* __restrict__ xp,
    const float* __restrict__ xdbl,
    const float* __restrict__ A_log,
    float* __restrict__ P, float* __restrict__ Q,
    float* __restrict__ yloc)
{
    __shared__ float sB[TSEG][DS];
    __shared__ float sC[TSEG][DS];
    __shared__ float sdt[TSEG][16];
    __shared__ float sx[TSEG][16];

    const int b   = blockIdx.x / (DI / 16);
    const int d0  = (blockIdx.x % (DI / 16)) * 16;
    const int seg = blockIdx.y;
    const int t0  = seg * TSEG;
    const int tid = threadIdx.x;
    const int warp = tid >> 5, lane = tid & 31;
    const int sub = lane >> 4, n = lane & 15;
    const int dl  = warp * 2 + sub;
    const int d   = d0 + dl;

    for (int e = tid; e < TSEG * DS; e += 256) {
        int t = e >> 4, nn = e & 15;
        const float* row = &xdbl[(b * LEN + t0 + t) * 96];
        sB[t][nn] = row[64 + nn];
        sC[t][nn] = row[80 + nn];
    }
    for (int e = tid; e < TSEG * 16; e += 256) {
        int t = e >> 4, dd = e & 15;
        int gi = (b * LEN + t0 + t) * DI + d0 + dd;
        sdt[t][dd] = dtp[gi];
        sx[t][dd]  = xp[gi];
    }
    __syncthreads();

    const float a = -__expf(A_log[d * DS + n]);
    float h = 0.f, p = 1.f;

    for (int t = 0; t < TSEG; t++) {
        float dt = sdt[t][dl];
        float xv = sx[t][dl];
        float dA = __expf(dt * a);
        h = fmaf(dA, h, dt * sB[t][n] * xv);
        p *= dA;
        float part = h * sC[t][n];
        part += __shfl_xor_sync(0xffffffffu, part, 8);
        part += __shfl_xor_sync(0xffffffffu, part, 4);
        part += __shfl_xor_sync(0xffffffffu, part, 2);
        part += __shfl_xor_sync(0xffffffffu, part, 1);
        if (n == 0)
            yloc[(b * LEN + t0 + t) * DI + d] = part;
    }

    const int pi = ((b * DI + d) * DS + n) * NSEG + seg;
    P[pi] = p;
    Q[pi] = h;
}

__global__ void scanB(const float* __restrict__ P,
                      const float* __restrict__ Q,
                      float* __restrict__ hin)
{
    int i = blockIdx.x * 256 + threadIdx.x;     // over BSZ*DI*DS
    if (i >= BSZ * DI * DS) return;
    const int base = i * NSEG;
    float h = 0.f;
#pragma unroll
    for (int s = 0; s < NSEG; s++) {
        hin[base + s] = h;
        h = fmaf(P[base + s], h, Q[base + s]);
    }
}

__global__ void __launch_bounds__(256) scanC(
    const float* __restrict__ dtp,
    const float* __restrict__ xp,
    const float* __restrict__ xdbl,
    const float* __restrict__ A_log,
    const float* __restrict__ Dp,
    const float* __restrict__ xz,
    const float* __restrict__ hin,
    const float* __restrict__ yloc,
    __half* __restrict__ y)
{
    __shared__ float sC[TSEG][DS];
    __shared__ float sdt[TSEG][16];
    __shared__ float sx[TSEG][16];
    __shared__ float sz[TSEG][16];

    const int b   = blockIdx.x / (DI / 16);
    const int d0  = (blockIdx.x % (DI / 16)) * 16;
    const int seg = blockIdx.y;
    const int t0  = seg * TSEG;
    const int tid = threadIdx.x;
    const int warp = tid >> 5, lane = tid & 31;
    const int sub = lane >> 4, n = lane & 15;
    const int dl  = warp * 2 + sub;
    const int d   = d0 + dl;

    for (int e = tid; e < TSEG * DS; e += 256) {
        int t = e >> 4, nn = e & 15;
        sC[t][nn] = xdbl[(b * LEN + t0 + t) * 96 + 80 + nn];
    }
    for (int e = tid; e < TSEG * 16; e += 256) {
        int t = e >> 4, dd = e & 15;
        int bl = b * LEN + t0 + t;
        sdt[t][dd] = dtp[bl * DI + d0 + dd];
        sx[t][dd]  = xp[bl * DI + d0 + dd];
        sz[t][dd]  = xz[bl * (2 * DI) + DI + d0 + dd];
    }
    __syncthreads();

    const float a  = -__expf(A_log[d * DS + n]);
    const float Dv = Dp[d];
    const float hv = hin[((b * DI + d) * DS + n) * NSEG + seg];
    float ap = 1.f;

    for (int t = 0; t < TSEG; t++) {
        float dt = sdt[t][dl];
        float dA = __expf(dt * a);
        ap *= dA;
        float corr = ap * hv * sC[t][n];
        corr += __shfl_xor_sync(0xffffffffu, corr, 8);
        corr += __shfl_xor_sync(0xffffffffu, corr, 4);
        corr += __shfl_xor_sync(0xffffffffu, corr, 2);
        corr += __shfl_xor_sync(0xffffffffu, corr, 1);
        if (n == 0) {
            int bl = b * LEN + t0 + t;
            float xv = sx[t][dl];
            float v  = yloc[bl * DI + d] + corr + xv * Dv;
            float z  = sz[t][dl];
            v *= z / (1.f + __expf(-z));
            y[bl * DI + d] = __float2half_rn(v);
        }
    }
}

// ---------------------------------------------------------------------------
extern "C" void kernel_launch(void* const* d_in, const int* in_sizes, int n_in,
                              void* d_out, int out_size)
{
    const float* hidden = (const float*)d_in[0];
    const float* in_w   = (const float*)d_in[1];
    const float* conv_w = (const float*)d_in[2];
    const float* conv_b = (const float*)d_in[3];
    const float* xproj  = (const float*)d_in[4];
    const float* dtw    = (const float*)d_in[5];
    const float* dtb    = (const float*)d_in[6];
    const float* alog   = (const float*)d_in[7];
    const float* Dp     = (const float*)d_in[8];
    const float* outw   = (const float*)d_in[9];
    float* out = (float*)d_out;

    static float  *pxz = nullptr, *px = nullptr, *pxd = nullptr, *pdt = nullptr,
                  *pyl = nullptr, *pP = nullptr, *pQ = nullptr, *phin = nullptr;
    static __half *pxh = nullptr, *pdtrh = nullptr, *pyh = nullptr,
                  *phid = nullptr, *pinw = nullptr, *pxpw = nullptr,
                  *pdtw = nullptr, *potw = nullptr;
    if (!pxz) {
        cudaGetSymbolAddress((void**)&pxz,   g_xz);
        cudaGetSymbolAddress((void**)&px,    g_x);
        cudaGetSymbolAddress((void**)&pxd,   g_xdbl);
        cudaGetSymbolAddress((void**)&pdt,   g_dt);
        cudaGetSymbolAddress((void**)&pyl,   g_yloc);
        cudaGetSymbolAddress((void**)&pP,    g_P);
        cudaGetSymbolAddress((void**)&pQ,    g_Q);
        cudaGetSymbolAddress((void**)&phin,  g_hin);
        cudaGetSymbolAddress((void**)&pxh,   g_xh);
        cudaGetSymbolAddress((void**)&pdtrh, g_dtrh);
        cudaGetSymbolAddress((void**)&pyh,   g_yh);
        cudaGetSymbolAddress((void**)&phid,  g_hidh);
        cudaGetSymbolAddress((void**)&pinw,  g_inwh);
        cudaGetSymbolAddress((void**)&pxpw,  g_xpwh);
        cudaGetSymbolAddress((void**)&pdtw,  g_dtwh);
        cudaGetSymbolAddress((void**)&potw,  g_otwh);
        cudaFuncSetAttribute(gemm_h,
            cudaFuncAttributeMaxDynamicSharedMemorySize, SMEM_BYTES);
    }

    // #1 weights -> fp16
    convert_w<<<(CWT + 511) / 512, 512>>>(in_w, xproj, dtw, outw);
    // #2 hidden -> fp16
    convert_hid<<<(CS0 / 4 + 511) / 512, 512>>>(hidden);
    // #3 zero split-K accumulator
    zero_kernel<<<(MROWS * 96 + 511) / 512, 512>>>(pxd, MROWS * 96);

    // #4 xz = hidden @ in_proj_w^T          (2048 x 4096 x 1024)  [profiled]
    gemm_h<<<dim3(2 * DI / 128, MROWS / 128, 1), 256, SMEM_BYTES>>>(
        phid, DM, pinw, DM, pxz, 2 * DI, 2 * DI, DM, nullptr, 0, 0);

    // #5 x = silu(conv1d(x) + b)
    conv_silu_kernel<<<(MROWS * DI) / 256, 256>>>(pxz, conv_w, conv_b, px, pxh);

    // #6 x_dbl = x @ x_proj_w^T             (2048 x 96 x 2048), split-K=8
    gemm_h<<<dim3(1, MROWS / 128, 8), 256, SMEM_BYTES>>>(
        pxh, DI, pxpw, DI, pxd, 96, 96, DI / 8, nullptr, 0, 1);

    // #7 dt_r slice -> half
    dtr2h_kernel<<<(MROWS * DR + 511) / 512, 512>>>(pxd, pdtrh);

    // #8 dt = softplus(dt_r @ dt_proj_w^T + b)   (2048 x 2048 x 64)
    gemm_h<<<dim3(DI / 128, MROWS / 128, 1), 256, SMEM_BYTES>>>(
        pdtrh, DR, pdtw, DR, pdt, DI, DI, DR, dtb, 1, 0);

    // #9-#11 segmented selective scan
    scanA<<<dim3(BSZ * (DI / 16), NSEG), 256>>>(pdt, px, pxd, alog, pP, pQ, pyl);
    scanB<<<(BSZ * DI * DS + 255) / 256, 256>>>(pP, pQ, phin);
    scanC<<<dim3(BSZ * (DI / 16), NSEG), 256>>>(pdt, px, pxd, alog, Dp, pxz,
                                                phin, pyl, pyh);

    // #12 out = y @ out_proj_w^T            (2048 x 1024 x 2048)
    gemm_h<<<dim3(DM / 128, MROWS / 128, 1), 256, SMEM_BYTES>>>(
        pyh, DI, potw, DI, out, DM, DM, DI, nullptr, 0, 0);
}

// round 11
// speedup vs baseline: 3.6322x; 1.6264x over previous
#include <cuda_runtime.h>
#include <cuda_fp16.h>
#include <cstdint>

// Problem dims (fixed by the reference)
#define BSZ   2
#define LEN   1024
#define DM    1024
#define DI    2048
#define DS    16
#define DR    64
#define MROWS (BSZ*LEN)     // 2048
#define NSEG  16
#define TSEG  (LEN/NSEG)    // 64

// ---------------------------------------------------------------------------
// Scratch (allocation-free: __device__ globals)
// ---------------------------------------------------------------------------
__device__ float  g_xz   [MROWS * 2 * DI];  // in_proj out (x | z), fp32
__device__ float  g_x    [MROWS * DI];      // conv+silu out fp32 (scan)
__device__ __half g_xh   [MROWS * DI];      // conv+silu out half (x_proj A)
__device__ float  g_xdbl [MROWS * 96];      // x_proj out (dt_r | B | C) fp32
__device__ __half g_dtrh [MROWS * DR];      // x_dbl[:, :64] half (dt_proj A)
__device__ float  g_dt   [MROWS * DI];      // softplus dt fp32
__device__ __half g_yh   [MROWS * DI];      // gated scan out half (out_proj A)
__device__ float  g_P    [BSZ * DI * NSEG * DS];
__device__ float  g_Q    [BSZ * DI * NSEG * DS];
__device__ float  g_hin  [BSZ * DI * NSEG * DS];

__device__ __half g_hidh [MROWS * DM];      // hidden in half
__device__ __half g_inwh [2 * DI * DM];     // in_proj_w half
__device__ __half g_xpwh [96 * DI];         // x_proj_w half
__device__ __half g_dtwh [DI * DR];         // dt_proj_w half
__device__ __half g_otwh [DM * DI];         // out_proj_w half

__device__ __forceinline__ void cpa16(void* dst, const void* src, int sz) {
    uint32_t d = (uint32_t)__cvta_generic_to_shared(dst);
    asm volatile("cp.async.cg.shared.global [%0], [%1], 16, %2;\n"
                 :: "r"(d), "l"(src), "r"(sz) : "memory");
}

__device__ __forceinline__ void ldmx4(uint32_t& r0, uint32_t& r1,
                                      uint32_t& r2, uint32_t& r3,
                                      const void* p) {
    uint32_t a = (uint32_t)__cvta_generic_to_shared(p);
    asm volatile("ldmatrix.sync.aligned.m8n8.x4.shared.b16 {%0,%1,%2,%3}, [%4];"
                 : "=r"(r0), "=r"(r1), "=r"(r2), "=r"(r3) : "r"(a));
}

// ---------------------------------------------------------------------------
// fp16 GEMM (unchanged from round 9): C[M,N] (+)= A*W^T, fp32 acc.
// CTA 128x128, 256 thr, warp tile 64x32, NS=3 cp.async pipeline.
// ---------------------------------------------------------------------------
#define BK 32
#define NS 3
#define SSTR 40
#define ABUF (128 * SSTR)
#define SMEM_BYTES (2 * NS * ABUF * 2)

__global__ void __launch_bounds__(256, 2) gemm_h(
    const __half* __restrict__ A, int lda,
    const __half* __restrict__ W, int ldw,
    float* __restrict__ C, int ldc,
    int N, int ksplit,
    const float* __restrict__ bias, int act, int atomic)
{
    extern __shared__ __half sm[];
    __half* Asm = sm;
    __half* Wsm = sm + NS * ABUF;

    const int bm   = blockIdx.y * 128;
    const int bn   = blockIdx.x * 128;
    const int kb   = blockIdx.z * ksplit;
    const int tid  = threadIdx.x;
    const int warp = tid >> 5;
    const int lane = tid & 31;
    const int wm   = (warp & 1) * 64;
    const int wn   = (warp >> 1) * 32;
    const int g    = lane >> 2;
    const int tg   = lane & 3;

    const int lr = tid >> 1;
    const int lc = (tid & 1) * 16;
    const bool wrow_ok = (bn + lr < N);
    const __half* ap = &A[(bm + lr) * lda + kb + lc];
    const __half* wp = &W[(bn + lr) * ldw + kb + lc];
    __half* asd = &Asm[lr * SSTR + lc];
    __half* wsd = &Wsm[lr * SSTR + lc];

    const int arow = wm + (lane & 15);
    const int akof = (lane >> 4) * 8;
    const int brow = wn + (lane & 7) + ((lane >> 4) << 3);
    const int bkof = ((lane >> 3) & 1) * 8;

    float acc[4][4][4];
#pragma unroll
    for (int i = 0; i < 4; i++)
#pragma unroll
        for (int j = 0; j < 4; j++)
#pragma unroll
            for (int c = 0; c < 4; c++) acc[i][j][c] = 0.f;

    const int nstage = ksplit / BK;

#pragma unroll
    for (int s = 0; s < NS - 1; s++) {
        const int ks  = s * BK;
        const int vz  = (s < nstage) ? 16 : 0;
        const int vzw = (vz && wrow_ok) ? 16 : 0;
        cpa16(asd + (size_t)s * ABUF,     ap + ks,     vz);
        cpa16(asd + (size_t)s * ABUF + 8, ap + ks + 8, vz);
        cpa16(wsd + (size_t)s * ABUF,     wp + ks,     vzw);
        cpa16(wsd + (size_t)s * ABUF + 8, wp + ks + 8, vzw);
        asm volatile("cp.async.commit_group;" ::: "memory");
    }

    for (int s = 0; s < nstage; s++) {
        const int buf = s % NS;
        asm volatile("cp.async.wait_group %0;" :: "n"(NS - 2) : "memory");
        __syncthreads();

        {
            const int sp  = s + NS - 1;
            const int pb  = sp % NS;
            const int ks  = sp * BK;
            const int vz  = (sp < nstage) ? 16 : 0;
            const int vzw = (vz && wrow_ok) ? 16 : 0;
            cpa16(asd + (size_t)pb * ABUF,     ap + ks,     vz);
            cpa16(asd + (size_t)pb * ABUF + 8, ap + ks + 8, vz);
            cpa16(wsd + (size_t)pb * ABUF,     wp + ks,     vzw);
            cpa16(wsd + (size_t)pb * ABUF + 8, wp + ks + 8, vzw);
            asm volatile("cp.async.commit_group;" ::: "memory");
        }

        const __half* ab = Asm + (size_t)buf * ABUF;
        const __half* wb = Wsm + (size_t)buf * ABUF;
#pragma unroll
        for (int kk = 0; kk < BK; kk += 16) {
            uint32_t a[4][4], b[8];
#pragma unroll
            for (int mi = 0; mi < 4; mi++)
                ldmx4(a[mi][0], a[mi][1], a[mi][2], a[mi][3],
                      ab + (arow + 16 * mi) * SSTR + kk + akof);
            ldmx4(b[0], b[1], b[2], b[3],
                  wb + brow * SSTR + kk + bkof);
            ldmx4(b[4], b[5], b[6], b[7],
                  wb + (brow + 16) * SSTR + kk + bkof);
#pragma unroll
            for (int mi = 0; mi < 4; mi++)
#pragma unroll
                for (int jf = 0; jf < 4; jf++)
                    asm volatile(
                        "mma.sync.aligned.m16n8k16.row.col.f32.f16.f16.f32 "
                        "{%0,%1,%2,%3},{%4,%5,%6,%7},{%8,%9},{%0,%1,%2,%3};"
                        : "+f"(acc[mi][jf][0]), "+f"(acc[mi][jf][1]),
                          "+f"(acc[mi][jf][2]), "+f"(acc[mi][jf][3])
                        : "r"(a[mi][0]), "r"(a[mi][1]),
                          "r"(a[mi][2]), "r"(a[mi][3]),
                          "r"(b[2 * jf]), "r"(b[2 * jf + 1]));
        }
    }

#pragma unroll
    for (int mi = 0; mi < 4; mi++)
#pragma unroll
        for (int jf = 0; jf < 4; jf++) {
            const int nn = bn + wn + jf * 8 + tg * 2;
            if (nn < N) {
                const int m0 = bm + wm + mi * 16 + g;
                float v0 = acc[mi][jf][0], v1 = acc[mi][jf][1];
                float v2 = acc[mi][jf][2], v3 = acc[mi][jf][3];
                if (act) {
                    const float b0 = bias[nn], b1 = bias[nn + 1];
                    v0 += b0; v1 += b1; v2 += b0; v3 += b1;
                    v0 = (v0 > 20.f) ? v0 : log1pf(__expf(v0));
                    v1 = (v1 > 20.f) ? v1 : log1pf(__expf(v1));
                    v2 = (v2 > 20.f) ? v2 : log1pf(__expf(v2));
                    v3 = (v3 > 20.f) ? v3 : log1pf(__expf(v3));
                }
                if (atomic) {
                    atomicAdd(&C[m0 * ldc + nn],           v0);
                    atomicAdd(&C[m0 * ldc + nn + 1],       v1);
                    atomicAdd(&C[(m0 + 8) * ldc + nn],     v2);
                    atomicAdd(&C[(m0 + 8) * ldc + nn + 1], v3);
                } else {
                    *(float2*)&C[m0 * ldc + nn]       = make_float2(v0, v1);
                    *(float2*)&C[(m0 + 8) * ldc + nn] = make_float2(v2, v3);
                }
            }
        }
}

// ---------------------------------------------------------------------------
// fp32 -> fp16 conversions
// ---------------------------------------------------------------------------
#define CS0 (MROWS * DM)
#define CS1 (2 * DI * DM)
#define CS2 (96 * DI)
#define CS3 (DI * DR)
#define CS4 (DM * DI)
#define CWT ((CS1 + CS2 + CS3 + CS4) / 4)

__global__ void convert_w(const float* __restrict__ inw,
                          const float* __restrict__ xpw,
                          const float* __restrict__ dtw,
                          const float* __restrict__ otw)
{
    int t = blockIdx.x * 512 + threadIdx.x;
    if (t >= CWT) return;
    int i = t * 4;
    const float* src; __half* dst; int off;
    if (i < CS1) {
        src = inw; dst = g_inwh; off = i;
    } else if ((i -= CS1) < CS2) {
        src = xpw; dst = g_xpwh; off = i;
    } else if ((i -= CS2) < CS3) {
        src = dtw; dst = g_dtwh; off = i;
    } else {
        src = otw; dst = g_otwh; off = i - CS3;
    }
    float4 v = *(const float4*)(src + off);
    *(__half2*)(dst + off)     = __floats2half2_rn(v.x, v.y);
    *(__half2*)(dst + off + 2) = __floats2half2_rn(v.z, v.w);
}

__global__ void convert_hid(const float* __restrict__ hid)
{
    int t = blockIdx.x * 512 + threadIdx.x;
    if (t >= CS0 / 4) return;
    int off = t * 4;
    float4 v = *(const float4*)(hid + off);
    *(__half2*)(g_hidh + off)     = __floats2half2_rn(v.x, v.y);
    *(__half2*)(g_hidh + off + 2) = __floats2half2_rn(v.z, v.w);
}

__global__ void dtr2h_kernel(const float* __restrict__ xdbl, __half* __restrict__ d)
{
    int i = blockIdx.x * 512 + threadIdx.x;
    if (i < MROWS * DR) {
        int r = i >> 6, c = i & 63;
        d[i] = __float2half_rn(xdbl[r * 96 + c]);
    }
}

__global__ void zero_kernel(float* __restrict__ p, int n)
{
    int i = blockIdx.x * 512 + threadIdx.x;
    if (i < n) p[i] = 0.f;
}

// ---------------------------------------------------------------------------
// Depthwise causal conv (K=4) + bias + SiLU.
// ---------------------------------------------------------------------------
__global__ void conv_silu_kernel(const float* __restrict__ xz,
                                 const float* __restrict__ w,
                                 const float* __restrict__ bias,
                                 float* __restrict__ xout,
                                 __half* __restrict__ xhout)
{
    int idx = blockIdx.x * blockDim.x + threadIdx.x;
    int d  = idx & (DI - 1);
    int bl = idx >> 11;
    int l  = bl & (LEN - 1);
    float accv = bias[d];
#pragma unroll
    for (int k = 0; k < 4; k++) {
        int ll = l + k - 3;
        if (ll >= 0)
            accv += xz[(bl + (ll - l)) * (2 * DI) + d] * w[d * 4 + k];
    }
    float v = accv / (1.f + __expf(-accv));
    xout[idx]  = v;
    xhout[idx] = __float2half_rn(v);
}

// ---------------------------------------------------------------------------
// Segmented selective scan, state-per-thread (16 states in registers).
// Phase A: per-segment (P, Q): P[n] = exp(a[n]*sum dt), Q[n] = h_end[n].
// Phase B: serial combine across 16 segments -> h_in.
// Phase C: re-scan each segment seeded with h_in; y = sum_n h*C + x*D,
//          gated by silu(z), written as half.
// Block = 256 threads = 256 d-channels of one (b, seg).
// ---------------------------------------------------------------------------
__global__ void __launch_bounds__(256) scanA(
    const float* __restrict__ dtp,
    const float* __restrict__ xp,
    const float* __restrict__ xdbl,
    const float* __restrict__ A_log,
    float* __restrict__ P, float* __restrict__ Q)
{
    __shared__ float sB[TSEG][DS];

    const int d   = blockIdx.x * 256 + threadIdx.x;
    const int seg = blockIdx.y;
    const int b   = blockIdx.z;
    const int t0  = seg * TSEG;

    for (int e = threadIdx.x; e < TSEG * DS; e += 256) {
        int t = e >> 4, n = e & 15;
        sB[t][n] = xdbl[(b * LEN + t0 + t) * 96 + 64 + n];
    }
    __syncthreads();

    float a[DS], h[DS];
#pragma unroll
    for (int n = 0; n < DS; n++) {
        a[n] = -__expf(A_log[d * DS + n]);
        h[n] = 0.f;
    }

    const int gi = (b * LEN + t0) * DI + d;
    float Sdt = 0.f;
    float dt_c = dtp[gi], x_c = xp[gi];

    for (int t = 0; t < TSEG; t++) {
        float dt_n = 0.f, x_n = 0.f;
        if (t + 1 < TSEG) {
            dt_n = dtp[gi + (t + 1) * DI];
            x_n  = xp[gi + (t + 1) * DI];
        }
        const float dtx = dt_c * x_c;
        Sdt += dt_c;
        float bb[DS];
        *(float4*)&bb[0]  = *(const float4*)&sB[t][0];
        *(float4*)&bb[4]  = *(const float4*)&sB[t][4];
        *(float4*)&bb[8]  = *(const float4*)&sB[t][8];
        *(float4*)&bb[12] = *(const float4*)&sB[t][12];
#pragma unroll
        for (int n = 0; n < DS; n++) {
            float dA = __expf(dt_c * a[n]);
            h[n] = fmaf(dA, h[n], bb[n] * dtx);
        }
        dt_c = dt_n; x_c = x_n;
    }

    const int pb = ((b * DI + d) * NSEG + seg) * DS;
#pragma unroll
    for (int n = 0; n < DS; n += 4) {
        float4 pv = make_float4(__expf(a[n] * Sdt),     __expf(a[n + 1] * Sdt),
                                __expf(a[n + 2] * Sdt), __expf(a[n + 3] * Sdt));
        *(float4*)&P[pb + n] = pv;
        *(float4*)&Q[pb + n] = make_float4(h[n], h[n + 1], h[n + 2], h[n + 3]);
    }
}

__global__ void scanB(const float* __restrict__ P,
                      const float* __restrict__ Q,
                      float* __restrict__ hin)
{
    int i = blockIdx.x * 256 + threadIdx.x;     // over BSZ*DI
    if (i >= BSZ * DI) return;
    float h[DS];
#pragma unroll
    for (int n = 0; n < DS; n++) h[n] = 0.f;
    const int base = i * NSEG * DS;
    for (int s = 0; s < NSEG; s++) {
        const int o = base + s * DS;
#pragma unroll
        for (int n = 0; n < DS; n += 4) {
            float4 p = *(const float4*)&P[o + n];
            float4 q = *(const float4*)&Q[o + n];
            *(float4*)&hin[o + n] = make_float4(h[n], h[n+1], h[n+2], h[n+3]);
            h[n]     = fmaf(p.x, h[n],     q.x);
            h[n + 1] = fmaf(p.y, h[n + 1], q.y);
            h[n + 2] = fmaf(p.z, h[n + 2], q.z);
            h[n + 3] = fmaf(p.w, h[n + 3], q.w);
        }
    }
}

__global__ void __launch_bounds__(256) scanC(
    const float* __restrict__ dtp,
    const float* __restrict__ xp,
    const float* __restrict__ xdbl,
    const float* __restrict__ A_log,
    const float* __restrict__ Dp,
    const float* __restrict__ xz,
    const float* __restrict__ hin,
    __half* __restrict__ y)
{
    __shared__ float sB[TSEG][DS];
    __shared__ float sC[TSEG][DS];

    const int d   = blockIdx.x * 256 + threadIdx.x;
    const int seg = blockIdx.y;
    const int b   = blockIdx.z;
    const int t0  = seg * TSEG;

    for (int e = threadIdx.x; e < TSEG * DS; e += 256) {
        int t = e >> 4, n = e & 15;
        const float* row = &xdbl[(b * LEN + t0 + t) * 96];
        sB[t][n] = row[64 + n];
        sC[t][n] = row[80 + n];
    }
    __syncthreads();

    float a[DS], h[DS];
#pragma unroll
    for (int n = 0; n < DS; n++)
        a[n] = -__expf(A_log[d * DS + n]);
    {
        const int hb = ((b * DI + d) * NSEG + seg) * DS;
#pragma unroll
        for (int n = 0; n < DS; n += 4)
            *(float4*)&h[n] = *(const float4*)&hin[hb + n];
    }
    const float Dv = Dp[d];

    const int gi = (b * LEN + t0) * DI + d;
    const int zi = (b * LEN + t0) * 2 * DI + DI + d;
    float dt_c = dtp[gi], x_c = xp[gi], z_c = xz[zi];

    for (int t = 0; t < TSEG; t++) {
        float dt_n = 0.f, x_n = 0.f, z_n = 0.f;
        if (t + 1 < TSEG) {
            dt_n = dtp[gi + (t + 1) * DI];
            x_n  = xp[gi + (t + 1) * DI];
            z_n  = xz[zi + (t + 1) * 2 * DI];
        }
        const float dtx = dt_c * x_c;
        float bb[DS], cc[DS];
        *(float4*)&bb[0]  = *(const float4*)&sB[t][0];
        *(float4*)&bb[4]  = *(const float4*)&sB[t][4];
        *(float4*)&bb[8]  = *(const float4*)&sB[t][8];
        *(float4*)&bb[12] = *(const float4*)&sB[t][12];
        *(float4*)&cc[0]  = *(const float4*)&sC[t][0];
        *(float4*)&cc[4]  = *(const float4*)&sC[t][4];
        *(float4*)&cc[8]  = *(const float4*)&sC[t][8];
        *(float4*)&cc[12] = *(const float4*)&sC[t][12];
        float yv = 0.f;
#pragma unroll
        for (int n = 0; n < DS; n++) {
            float dA = __expf(dt_c * a[n]);
            h[n] = fmaf(dA, h[n], bb[n] * dtx);
            yv = fmaf(h[n], cc[n], yv);
        }
        float v  = yv + x_c * Dv;
        float gz = z_c / (1.f + __expf(-z_c));
        y[gi + t * DI] = __float2half_rn(v * gz);
        dt_c = dt_n; x_c = x_n; z_c = z_n;
    }
}

// ---------------------------------------------------------------------------
extern "C" void kernel_launch(void* const* d_in, const int* in_sizes, int n_in,
                              void* d_out, int out_size)
{
    const float* hidden = (const float*)d_in[0];
    const float* in_w   = (const float*)d_in[1];
    const float* conv_w = (const float*)d_in[2];
    const float* conv_b = (const float*)d_in[3];
    const float* xproj  = (const float*)d_in[4];
    const float* dtw    = (const float*)d_in[5];
    const float* dtb    = (const float*)d_in[6];
    const float* alog   = (const float*)d_in[7];
    const float* Dp     = (const float*)d_in[8];
    const float* outw   = (const float*)d_in[9];
    float* out = (float*)d_out;

    static float  *pxz = nullptr, *px = nullptr, *pxd = nullptr, *pdt = nullptr,
                  *pP = nullptr, *pQ = nullptr, *phin = nullptr;
    static __half *pxh = nullptr, *pdtrh = nullptr, *pyh = nullptr,
                  *phid = nullptr, *pinw = nullptr, *pxpw = nullptr,
                  *pdtw = nullptr, *potw = nullptr;
    if (!pxz) {
        cudaGetSymbolAddress((void**)&pxz,   g_xz);
        cudaGetSymbolAddress((void**)&px,    g_x);
        cudaGetSymbolAddress((void**)&pxd,   g_xdbl);
        cudaGetSymbolAddress((void**)&pdt,   g_dt);
        cudaGetSymbolAddress((void**)&pP,    g_P);
        cudaGetSymbolAddress((void**)&pQ,    g_Q);
        cudaGetSymbolAddress((void**)&phin,  g_hin);
        cudaGetSymbolAddress((void**)&pxh,   g_xh);
        cudaGetSymbolAddress((void**)&pdtrh, g_dtrh);
        cudaGetSymbolAddress((void**)&pyh,   g_yh);
        cudaGetSymbolAddress((void**)&phid,  g_hidh);
        cudaGetSymbolAddress((void**)&pinw,  g_inwh);
        cudaGetSymbolAddress((void**)&pxpw,  g_xpwh);
        cudaGetSymbolAddress((void**)&pdtw,  g_dtwh);
        cudaGetSymbolAddress((void**)&potw,  g_otwh);
        cudaFuncSetAttribute(gemm_h,
            cudaFuncAttributeMaxDynamicSharedMemorySize, SMEM_BYTES);
    }

    // #1 weights -> fp16
    convert_w<<<(CWT + 511) / 512, 512>>>(in_w, xproj, dtw, outw);
    // #2 hidden -> fp16
    convert_hid<<<(CS0 / 4 + 511) / 512, 512>>>(hidden);
    // #3 zero split-K accumulator
    zero_kernel<<<(MROWS * 96 + 511) / 512, 512>>>(pxd, MROWS * 96);

    // #4 xz = hidden @ in_proj_w^T          (2048 x 4096 x 1024)  [profiled]
    gemm_h<<<dim3(2 * DI / 128, MROWS / 128, 1), 256, SMEM_BYTES>>>(
        phid, DM, pinw, DM, pxz, 2 * DI, 2 * DI, DM, nullptr, 0, 0);

    // #5 x = silu(conv1d(x) + b)
    conv_silu_kernel<<<(MROWS * DI) / 256, 256>>>(pxz, conv_w, conv_b, px, pxh);

    // #6 x_dbl = x @ x_proj_w^T             (2048 x 96 x 2048), split-K=8
    gemm_h<<<dim3(1, MROWS / 128, 8), 256, SMEM_BYTES>>>(
        pxh, DI, pxpw, DI, pxd, 96, 96, DI / 8, nullptr, 0, 1);

    // #7 dt_r slice -> half
    dtr2h_kernel<<<(MROWS * DR + 511) / 512, 512>>>(pxd, pdtrh);

    // #8 dt = softplus(dt_r @ dt_proj_w^T + b)   (2048 x 2048 x 64)
    gemm_h<<<dim3(DI / 128, MROWS / 128, 1), 256, SMEM_BYTES>>>(
        pdtrh, DR, pdtw, DR, pdt, DI, DI, DR, dtb, 1, 0);

    // #9-#11 segmented selective scan (state-per-thread)
    scanA<<<dim3(DI / 256, NSEG, BSZ), 256>>>(pdt, px, pxd, alog, pP, pQ);
    scanB<<<(BSZ * DI + 255) / 256, 256>>>(pP, pQ, phin);
    scanC<<<dim3(DI / 256, NSEG, BSZ), 256>>>(pdt, px, pxd, alog, Dp, pxz,
                                              phin, pyh);

    // #12 out = y @ out_proj_w^T            (2048 x 1024 x 2048)
    gemm_h<<<dim3(DM / 128, MROWS / 128, 1), 256, SMEM_BYTES>>>(
        pyh, DI, potw, DI, out, DM, DM, DI, nullptr, 0, 0);
}